// round 11
// baseline (speedup 1.0000x reference)
#include <cuda_runtime.h>
#include <cuda_bf16.h>
#include <cstdint>
#include <math.h>

#define N_NODES 50000
#define N_EDGES 640000
#define F 128
#define F4 32
#define NCLASS 40
#define SCAN_BLKS 49

// ---------------- scratch (static __device__, no allocation) ----------------
__device__ float4        g_acta[N_NODES * F4];  // activations ping
__device__ float4        g_actb[N_NODES * F4];  // activations pong
__device__ __nv_bfloat16 g_wthi[4 * F * F];     // W^T hi, all 4 layers
__device__ __nv_bfloat16 g_wtlo[4 * F * F];     // W^T lo
__device__ int g_cnt[N_NODES];
__device__ int g_off[N_NODES + 1];
__device__ int g_cur[N_NODES];
__device__ int g_srcs[N_EDGES];
__device__ int g_bsum[64];
__device__ int g_bpre[64];

// ---------------- prep: zero counts + all 4 W -> Wt hi/lo bf16 ----------------
__global__ void prep_kernel(const float* __restrict__ W1,
                            const float* __restrict__ W2,
                            const float* __restrict__ W3,
                            const float* __restrict__ W4) {
    int i = blockIdx.x * blockDim.x + threadIdx.x;
    if (i < 4 * F * F) {
        int layer = i >> 14;
        int r = i & (F * F - 1);
        int k = r >> 7, n = r & 127;
        const float* W = (layer == 0) ? W1 : (layer == 1) ? W2 : (layer == 2) ? W3 : W4;
        float w = W[k * F + n];
        __nv_bfloat16 h = __float2bfloat16(w);
        g_wthi[layer * F * F + n * F + k] = h;
        g_wtlo[layer * F * F + n * F + k] = __float2bfloat16(w - __bfloat162float(h));
    }
    int z = i - 4 * F * F;
    if (z >= 0 && z < N_NODES) g_cnt[z] = 0;
}

// ---------------- CSR build ----------------
__global__ void hist_kernel(const int* __restrict__ dst) {
    int e = blockIdx.x * blockDim.x + threadIdx.x;
    if (e < N_EDGES) atomicAdd(&g_cnt[dst[e]], 1);
}

__global__ void scanA_kernel() {
    __shared__ int sh[1024];
    int tid = threadIdx.x;
    int i = blockIdx.x * 1024 + tid;
    int v = (i < N_NODES) ? g_cnt[i] : 0;
    sh[tid] = v;
    __syncthreads();
    for (int off = 1; off < 1024; off <<= 1) {
        int t = (tid >= off) ? sh[tid - off] : 0;
        __syncthreads();
        sh[tid] += t;
        __syncthreads();
    }
    if (i < N_NODES) g_off[i] = sh[tid] - v;
    if (tid == 1023) g_bsum[blockIdx.x] = sh[1023];
}

__global__ void scanB_kernel() {
    __shared__ int sh[64];
    int tid = threadIdx.x;
    int v = (tid < SCAN_BLKS) ? g_bsum[tid] : 0;
    sh[tid] = v;
    __syncthreads();
    for (int off = 1; off < 64; off <<= 1) {
        int t = (tid >= off) ? sh[tid - off] : 0;
        __syncthreads();
        sh[tid] += t;
        __syncthreads();
    }
    if (tid < SCAN_BLKS) g_bpre[tid] = sh[tid] - v;
    if (tid == 63) g_off[N_NODES] = sh[63];
}

__global__ void scanC_kernel() {
    int i = blockIdx.x * 1024 + threadIdx.x;
    if (i < N_NODES) {
        int o = g_off[i] + g_bpre[blockIdx.x];
        g_off[i] = o;
        g_cur[i] = o;
    }
}

__global__ void fill_kernel(const int* __restrict__ src,
                            const int* __restrict__ dst) {
    int e = blockIdx.x * blockDim.x + threadIdx.x;
    if (e < N_EDGES) {
        int d = dst[e];
        int p = atomicAdd(&g_cur[d], 1);
        g_srcs[p] = src[e];
    }
}

// ---------------- fused GCN layer: gather -> GEMM -> bias/L2norm/ReLU ----------------
#define PTX 136   // X full-row pitch (128 bf16 + 8 pad)
#define PTW 40    // W slab pitch (32 bf16 + 8 pad)
#define LAYER_SMEM ((2 * 128 * PTX + 2 * 128 * PTW) * 2 + 512 + 128 * 2 * 4)

#define LDSM_X4(r0,r1,r2,r3,addr) \
    asm volatile("ldmatrix.sync.aligned.m8n8.x4.shared.b16 {%0,%1,%2,%3}, [%4];" \
        : "=r"(r0),"=r"(r1),"=r"(r2),"=r"(r3) : "r"(addr))
#define LDSM_X2(r0,r1,addr) \
    asm volatile("ldmatrix.sync.aligned.m8n8.x2.shared.b16 {%0,%1}, [%2];" \
        : "=r"(r0),"=r"(r1) : "r"(addr))
#define MMA16816(d,a0,a1,a2,a3,b0,b1) \
    asm volatile("mma.sync.aligned.m16n8k16.row.col.f32.bf16.bf16.f32 " \
        "{%0,%1,%2,%3},{%4,%5,%6,%7},{%8,%9},{%0,%1,%2,%3};" \
        : "+f"(d[0]),"+f"(d[1]),"+f"(d[2]),"+f"(d[3]) \
        : "r"(a0),"r"(a1),"r"(a2),"r"(a3),"r"(b0),"r"(b1))

__device__ __forceinline__ unsigned int smem_u32(const void* p) {
    return (unsigned int)__cvta_generic_to_shared(p);
}

// INSEL: 0 = external x, 1 = g_acta, 2 = g_actb
// OUTSEL: 0 = external (x4out), 1 = g_acta, 2 = g_actb
template<int INSEL, int OUTSEL>
__global__ __launch_bounds__(256, 2)
void gcn_layer_kernel(const float4* __restrict__ Xext, int layer,
                      const float* __restrict__ bias,
                      float2* __restrict__ OUText, int nrows) {
    extern __shared__ __nv_bfloat16 sm_b[];
    __nv_bfloat16* xhi_s = sm_b;                   // [128][PTX]
    __nv_bfloat16* xlo_s = xhi_s + 128 * PTX;
    __nv_bfloat16* whi_s = xlo_s + 128 * PTX;      // [128][PTW]
    __nv_bfloat16* wlo_s = whi_s + 128 * PTW;
    float* b_s  = (float*)(wlo_s + 128 * PTW);     // [128]
    float* ss_s = b_s + 128;                       // [128][2]

    const int tid  = threadIdx.x;
    const int lane = tid & 31;
    const int w    = tid >> 5;
    const int wr   = (w & 3) * 32;
    const int wc   = (w >> 2) * 64;
    const int row0 = blockIdx.x * 128;
    const int woff = layer * (F * F / 8);

    if (tid < 128) b_s[tid] = bias[tid];

    // ---- phase 1: gather + sum + split straight into the MMA A-tile ----
    const float4* tab = (INSEL == 0) ? Xext : (INSEL == 1) ? g_acta : g_actb;
    for (int t = 0; t < 16; t++) {
        int r = w * 16 + t;
        int gn = row0 + r;
        float4 acc = make_float4(0.f, 0.f, 0.f, 0.f);
        if (gn < nrows) {
            int s = g_off[gn], e = g_off[gn + 1];
            int i = s;
            for (; i + 7 < e; i += 8) {
                int u[8];
                #pragma unroll
                for (int j = 0; j < 8; j++) u[j] = __ldg(&g_srcs[i + j]);
                float4 v[8];
                #pragma unroll
                for (int j = 0; j < 8; j++) v[j] = __ldg(&tab[u[j] * F4 + lane]);
                #pragma unroll
                for (int j = 0; j < 8; j++) {
                    acc.x += v[j].x; acc.y += v[j].y; acc.z += v[j].z; acc.w += v[j].w;
                }
            }
            for (; i + 1 < e; i += 2) {
                int u0 = __ldg(&g_srcs[i]), u1 = __ldg(&g_srcs[i + 1]);
                float4 v0 = __ldg(&tab[u0 * F4 + lane]);
                float4 v1 = __ldg(&tab[u1 * F4 + lane]);
                acc.x += v0.x + v1.x; acc.y += v0.y + v1.y;
                acc.z += v0.z + v1.z; acc.w += v0.w + v1.w;
            }
            if (i < e) {
                float4 v = __ldg(&tab[__ldg(&g_srcs[i]) * F4 + lane]);
                acc.x += v.x; acc.y += v.y; acc.z += v.z; acc.w += v.w;
            }
        }
        float vals[4] = {acc.x, acc.y, acc.z, acc.w};
        __nv_bfloat16 hi[4], lo[4];
        #pragma unroll
        for (int j = 0; j < 4; j++) {
            hi[j] = __float2bfloat16(vals[j]);
            lo[j] = __float2bfloat16(vals[j] - __bfloat162float(hi[j]));
        }
        int off = r * PTX + lane * 4;
        *(uint2*)(xhi_s + off) = *(uint2*)hi;
        *(uint2*)(xlo_s + off) = *(uint2*)lo;
    }
    __syncthreads();

    // ---- phase 2: MMA (W streamed in 32-k slabs) ----
    float acc[2][8][4];
    #pragma unroll
    for (int mt = 0; mt < 2; mt++)
        #pragma unroll
        for (int nt = 0; nt < 8; nt++)
            #pragma unroll
            for (int j = 0; j < 4; j++) acc[mt][nt][j] = 0.f;

    const int l15 = lane & 15;
    const int koA = (lane >> 4) << 3;
    const int koB = (l15 >> 3) << 3;

    for (int ks = 0; ks < 4; ks++) {
        #pragma unroll
        for (int i = tid; i < 1024; i += 256) {
            int whichW = i >> 9;
            int r = (i >> 2) & 127;
            int c = i & 3;
            int gidx = woff + r * 16 + ks * 4 + c;
            uint4 v = whichW ? ((const uint4*)g_wtlo)[gidx]
                             : ((const uint4*)g_wthi)[gidx];
            __nv_bfloat16* base = whichW ? wlo_s : whi_s;
            *(uint4*)(base + r * PTW + c * 8) = v;
        }
        __syncthreads();

        #pragma unroll
        for (int j = 0; j < 2; j++) {
            unsigned int ahi[2][4], alo[2][4];
            #pragma unroll
            for (int mt = 0; mt < 2; mt++) {
                int r = wr + mt * 16 + l15;
                LDSM_X4(ahi[mt][0], ahi[mt][1], ahi[mt][2], ahi[mt][3],
                        smem_u32(xhi_s + r * PTX + ks * 32 + j * 16 + koA));
                LDSM_X4(alo[mt][0], alo[mt][1], alo[mt][2], alo[mt][3],
                        smem_u32(xlo_s + r * PTX + ks * 32 + j * 16 + koA));
            }
            #pragma unroll
            for (int nt = 0; nt < 8; nt++) {
                int boff = (wc + nt * 8 + (l15 & 7)) * PTW + j * 16 + koB;
                unsigned int bh0, bh1, bl0, bl1;
                LDSM_X2(bh0, bh1, smem_u32(whi_s + boff));
                LDSM_X2(bl0, bl1, smem_u32(wlo_s + boff));
                #pragma unroll
                for (int mt = 0; mt < 2; mt++) {
                    MMA16816(acc[mt][nt], ahi[mt][0], ahi[mt][1], ahi[mt][2], ahi[mt][3], bh0, bh1);
                    MMA16816(acc[mt][nt], ahi[mt][0], ahi[mt][1], ahi[mt][2], ahi[mt][3], bl0, bl1);
                    MMA16816(acc[mt][nt], alo[mt][0], alo[mt][1], alo[mt][2], alo[mt][3], bh0, bh1);
                }
            }
        }
        __syncthreads();
    }

    // ---- epilogue: +bias, row L2-norm, ReLU, store ----
    const int rA = lane >> 2;
    const int cB = (lane & 3) * 2;
    float ssp[2][2];
    #pragma unroll
    for (int mt = 0; mt < 2; mt++) {
        ssp[mt][0] = 0.f; ssp[mt][1] = 0.f;
        #pragma unroll
        for (int nt = 0; nt < 8; nt++) {
            float b0 = b_s[wc + nt * 8 + cB];
            float b1 = b_s[wc + nt * 8 + cB + 1];
            acc[mt][nt][0] += b0; acc[mt][nt][1] += b1;
            acc[mt][nt][2] += b0; acc[mt][nt][3] += b1;
            ssp[mt][0] += acc[mt][nt][0] * acc[mt][nt][0] + acc[mt][nt][1] * acc[mt][nt][1];
            ssp[mt][1] += acc[mt][nt][2] * acc[mt][nt][2] + acc[mt][nt][3] * acc[mt][nt][3];
        }
        #pragma unroll
        for (int d = 1; d < 4; d <<= 1) {
            ssp[mt][0] += __shfl_xor_sync(0xFFFFFFFFu, ssp[mt][0], d);
            ssp[mt][1] += __shfl_xor_sync(0xFFFFFFFFu, ssp[mt][1], d);
        }
        if ((lane & 3) == 0) {
            ss_s[(wr + mt * 16 + rA) * 2 + (w >> 2)]     = ssp[mt][0];
            ss_s[(wr + mt * 16 + rA + 8) * 2 + (w >> 2)] = ssp[mt][1];
        }
    }
    __syncthreads();

    #pragma unroll
    for (int mt = 0; mt < 2; mt++) {
        int r0l = wr + mt * 16 + rA;
        float ss0 = ss_s[r0l * 2] + ss_s[r0l * 2 + 1];
        float ss1 = ss_s[(r0l + 8) * 2] + ss_s[(r0l + 8) * 2 + 1];
        float inv0 = 1.f / fmaxf(sqrtf(ss0), 1e-12f);
        float inv1 = 1.f / fmaxf(sqrtf(ss1), 1e-12f);
        int gr = row0 + r0l;
        #pragma unroll
        for (int nt = 0; nt < 8; nt++) {
            int col2 = (wc + nt * 8 + cB) >> 1;
            float2 v0 = make_float2(fmaxf(acc[mt][nt][0] * inv0, 0.f),
                                    fmaxf(acc[mt][nt][1] * inv0, 0.f));
            float2 v1 = make_float2(fmaxf(acc[mt][nt][2] * inv1, 0.f),
                                    fmaxf(acc[mt][nt][3] * inv1, 0.f));
            float2* A2 = (OUTSEL == 0) ? OUText :
                         (OUTSEL == 1) ? (float2*)g_acta : (float2*)g_actb;
            if (gr < nrows)     A2[gr * 64 + col2]       = v0;
            if (gr + 8 < nrows) A2[(gr + 8) * 64 + col2] = v1;
        }
    }
}

// ---------------- final linear + softmax ----------------
#define HEAD_SMEM (128 * 128 * 4 + 128 * 40 * 4 + 40 * 4)

__global__ __launch_bounds__(256)
void final_kernel(const float4* __restrict__ X4,
                  const float4* __restrict__ Wl,
                  const float* __restrict__ bl,
                  float* __restrict__ logits,
                  float* __restrict__ probs) {
    extern __shared__ float sm_f[];
    float4* xsh4 = (float4*)sm_f;
    float4* wsh4 = (float4*)(sm_f + 128 * 128);
    float*  blsh = sm_f + 128 * 128 + 128 * 40;
    int tid = threadIdx.x;
    int n0 = blockIdx.x * 128;

    for (int i = tid; i < 128 * 32; i += 256) {
        int n = i >> 5, c = i & 31;
        int gn = n0 + n;
        xsh4[i] = (gn < N_NODES) ? X4[gn * 32 + c] : make_float4(0.f, 0.f, 0.f, 0.f);
    }
    for (int i = tid; i < 1280; i += 256) wsh4[i] = Wl[i];
    if (tid < 40) blsh[tid] = bl[tid];
    __syncthreads();

    int node = tid >> 1;
    int half = tid & 1;
    int gn = n0 + node;

    float acc[20];
    #pragma unroll
    for (int j = 0; j < 20; j++) acc[j] = blsh[half * 20 + j];

    const float4* xrow = xsh4 + node * 32;
    #pragma unroll 4
    for (int k4 = 0; k4 < 32; k4++) {
        float4 xv = xrow[k4];
        float xs[4] = {xv.x, xv.y, xv.z, xv.w};
        #pragma unroll
        for (int kk = 0; kk < 4; kk++) {
            int k = k4 * 4 + kk;
            const float4* wrow = wsh4 + k * 10 + half * 5;
            #pragma unroll
            for (int c4 = 0; c4 < 5; c4++) {
                float4 wv = wrow[c4];
                acc[c4 * 4 + 0] += xs[kk] * wv.x;
                acc[c4 * 4 + 1] += xs[kk] * wv.y;
                acc[c4 * 4 + 2] += xs[kk] * wv.z;
                acc[c4 * 4 + 3] += xs[kk] * wv.w;
            }
        }
    }

    float m = -1e30f;
    #pragma unroll
    for (int j = 0; j < 20; j++) m = fmaxf(m, acc[j]);
    m = fmaxf(m, __shfl_xor_sync(0xFFFFFFFFu, m, 1));
    float sum = 0.f;
    float ex[20];
    #pragma unroll
    for (int j = 0; j < 20; j++) { ex[j] = expf(acc[j] - m); sum += ex[j]; }
    sum += __shfl_xor_sync(0xFFFFFFFFu, sum, 1);
    float inv = 1.f / sum;

    if (gn < N_NODES) {
        int base = gn * NCLASS + half * 20;
        #pragma unroll
        for (int j = 0; j < 20; j++) {
            logits[base + j] = acc[j];
            probs[base + j]  = ex[j] * inv;
        }
    }
}

// ---------------- launch ----------------
extern "C" void kernel_launch(void* const* d_in, const int* in_sizes, int n_in,
                              void* d_out, int out_size) {
    const float* x  = (const float*)d_in[0];
    const int*   ei = (const int*)d_in[1];
    const float* W1 = (const float*)d_in[2];
    const float* b1 = (const float*)d_in[3];
    const float* W2 = (const float*)d_in[4];
    const float* b2 = (const float*)d_in[5];
    const float* W3 = (const float*)d_in[6];
    const float* b3 = (const float*)d_in[7];
    const float* W4 = (const float*)d_in[8];
    const float* b4 = (const float*)d_in[9];
    const float* Wl = (const float*)d_in[10];
    const float* bl = (const float*)d_in[11];

    const int* src = ei;
    const int* dst = ei + N_EDGES;

    float* out    = (float*)d_out;
    float* logits = out;
    float* probs  = out + N_NODES * NCLASS;
    float* x4out  = out + 2 * N_NODES * NCLASS;

    const int T = 256;
    const int layer_blocks = (N_NODES + 127) / 128;
    const int edge_blocks  = (N_EDGES + T - 1) / T;
    const int head_blocks  = (N_NODES + 127) / 128;
    const int prep_blocks  = (4 * F * F + N_NODES + T - 1) / T;

    cudaFuncSetAttribute((const void*)gcn_layer_kernel<0,1>, cudaFuncAttributeMaxDynamicSharedMemorySize, LAYER_SMEM);
    cudaFuncSetAttribute((const void*)gcn_layer_kernel<1,2>, cudaFuncAttributeMaxDynamicSharedMemorySize, LAYER_SMEM);
    cudaFuncSetAttribute((const void*)gcn_layer_kernel<2,1>, cudaFuncAttributeMaxDynamicSharedMemorySize, LAYER_SMEM);
    cudaFuncSetAttribute((const void*)gcn_layer_kernel<1,0>, cudaFuncAttributeMaxDynamicSharedMemorySize, LAYER_SMEM);
    cudaFuncSetAttribute((const void*)final_kernel, cudaFuncAttributeMaxDynamicSharedMemorySize, HEAD_SMEM);

    // prep + CSR
    prep_kernel<<<prep_blocks, T>>>(W1, W2, W3, W4);
    hist_kernel<<<edge_blocks, T>>>(dst);
    scanA_kernel<<<SCAN_BLKS, 1024>>>();
    scanB_kernel<<<1, 64>>>();
    scanC_kernel<<<SCAN_BLKS, 1024>>>();
    fill_kernel<<<edge_blocks, T>>>(src, dst);

    // 4 fused layers
    gcn_layer_kernel<0,1><<<layer_blocks, T, LAYER_SMEM>>>((const float4*)x, 0, b1, nullptr, N_NODES);
    gcn_layer_kernel<1,2><<<layer_blocks, T, LAYER_SMEM>>>(nullptr, 1, b2, nullptr, N_NODES);
    gcn_layer_kernel<2,1><<<layer_blocks, T, LAYER_SMEM>>>(nullptr, 2, b3, nullptr, N_NODES);
    gcn_layer_kernel<1,0><<<layer_blocks, T, LAYER_SMEM>>>(nullptr, 3, b4, (float2*)x4out, N_NODES);

    // head
    final_kernel<<<head_blocks, T, HEAD_SMEM>>>((const float4*)x4out, (const float4*)Wl, bl, logits, probs);
}

// round 12
// speedup vs baseline: 1.3791x; 1.3791x over previous
#include <cuda_runtime.h>
#include <cuda_bf16.h>
#include <cstdint>
#include <math.h>

#define N_NODES 50000
#define N_EDGES 640000
#define F 128
#define F4 32
#define NCLASS 40
#define SCAN_BLKS 49

// ---------------- scratch (static __device__, no allocation) ----------------
__device__ float4        g_agg[N_NODES * F4];   // aggregated sums (fp32)
__device__ float4        g_act[N_NODES * F4];   // layer activations (fp32)
__device__ __nv_bfloat16 g_wthi[4 * F * F];     // W^T hi, all 4 layers
__device__ __nv_bfloat16 g_wtlo[4 * F * F];     // W^T lo
__device__ int g_cnt[N_NODES];
__device__ int g_off[N_NODES + 1];
__device__ int g_cur[N_NODES];
__device__ int g_srcs[N_EDGES];
__device__ int g_bsum[64];
__device__ int g_bpre[64];

// ---------------- prep: zero counts + all 4 W -> Wt hi/lo bf16 ----------------
__global__ void prep_kernel(const float* __restrict__ W1,
                            const float* __restrict__ W2,
                            const float* __restrict__ W3,
                            const float* __restrict__ W4) {
    int i = blockIdx.x * blockDim.x + threadIdx.x;
    if (i < 4 * F * F) {
        int layer = i >> 14;
        int r = i & (F * F - 1);
        int k = r >> 7, n = r & 127;
        const float* W = (layer == 0) ? W1 : (layer == 1) ? W2 : (layer == 2) ? W3 : W4;
        float w = W[k * F + n];
        __nv_bfloat16 h = __float2bfloat16(w);
        g_wthi[layer * F * F + n * F + k] = h;
        g_wtlo[layer * F * F + n * F + k] = __float2bfloat16(w - __bfloat162float(h));
    }
    int z = i - 4 * F * F;
    if (z >= 0 && z < N_NODES) g_cnt[z] = 0;
}

// ---------------- CSR build ----------------
__global__ void hist_kernel(const int* __restrict__ dst) {
    int e = blockIdx.x * blockDim.x + threadIdx.x;
    if (e < N_EDGES) atomicAdd(&g_cnt[dst[e]], 1);
}

__global__ void scanA_kernel() {
    __shared__ int sh[1024];
    int tid = threadIdx.x;
    int i = blockIdx.x * 1024 + tid;
    int v = (i < N_NODES) ? g_cnt[i] : 0;
    sh[tid] = v;
    __syncthreads();
    for (int off = 1; off < 1024; off <<= 1) {
        int t = (tid >= off) ? sh[tid - off] : 0;
        __syncthreads();
        sh[tid] += t;
        __syncthreads();
    }
    if (i < N_NODES) g_off[i] = sh[tid] - v;
    if (tid == 1023) g_bsum[blockIdx.x] = sh[1023];
}

__global__ void scanB_kernel() {
    __shared__ int sh[64];
    int tid = threadIdx.x;
    int v = (tid < SCAN_BLKS) ? g_bsum[tid] : 0;
    sh[tid] = v;
    __syncthreads();
    for (int off = 1; off < 64; off <<= 1) {
        int t = (tid >= off) ? sh[tid - off] : 0;
        __syncthreads();
        sh[tid] += t;
        __syncthreads();
    }
    if (tid < SCAN_BLKS) g_bpre[tid] = sh[tid] - v;
    if (tid == 63) g_off[N_NODES] = sh[63];
}

__global__ void scanC_kernel() {
    int i = blockIdx.x * 1024 + threadIdx.x;
    if (i < N_NODES) {
        int o = g_off[i] + g_bpre[blockIdx.x];
        g_off[i] = o;
        g_cur[i] = o;
    }
}

__global__ void fill_kernel(const int* __restrict__ src,
                            const int* __restrict__ dst) {
    int e = blockIdx.x * blockDim.x + threadIdx.x;
    if (e < N_EDGES) {
        int d = dst[e];
        int p = atomicAdd(&g_cur[d], 1);
        g_srcs[p] = src[e];
    }
}

// ---------------- aggregate (pure sum, fp32 gather) ----------------
template<int SEL>
__global__ void agg_sum_kernel(const float4* __restrict__ Xext) {
    int node = (blockIdx.x * blockDim.x + threadIdx.x) >> 5;
    int lane = threadIdx.x & 31;
    if (node >= N_NODES) return;
    int s = g_off[node], e = g_off[node + 1];
    const float4* tab = (SEL == 0) ? Xext : g_act;
    float4 acc = make_float4(0.f, 0.f, 0.f, 0.f);
    int i = s;
    for (; i + 7 < e; i += 8) {
        int u[8];
        #pragma unroll
        for (int j = 0; j < 8; j++) u[j] = __ldg(&g_srcs[i + j]);
        float4 v[8];
        #pragma unroll
        for (int j = 0; j < 8; j++) v[j] = __ldg(&tab[u[j] * F4 + lane]);
        #pragma unroll
        for (int j = 0; j < 8; j++) {
            acc.x += v[j].x; acc.y += v[j].y; acc.z += v[j].z; acc.w += v[j].w;
        }
    }
    for (; i + 1 < e; i += 2) {
        int u0 = __ldg(&g_srcs[i]), u1 = __ldg(&g_srcs[i + 1]);
        float4 v0 = __ldg(&tab[u0 * F4 + lane]);
        float4 v1 = __ldg(&tab[u1 * F4 + lane]);
        acc.x += v0.x + v1.x; acc.y += v0.y + v1.y;
        acc.z += v0.z + v1.z; acc.w += v0.w + v1.w;
    }
    if (i < e) {
        float4 v = __ldg(&tab[__ldg(&g_srcs[i]) * F4 + lane]);
        acc.x += v.x; acc.y += v.y; acc.z += v.z; acc.w += v.w;
    }
    g_agg[node * F4 + lane] = acc;
}

// ---------------- GEMM + bias + L2norm + ReLU (+ fused head on last layer) ----------------
#define PT 40
#define GEMM_BASE (4 * 128 * PT * 2)            // 40960
#define BS_OFF    GEMM_BASE                      // bias: 512 B
#define SS_OFF    (GEMM_BASE + 512)              // ss: 1024 B
#define SMEM_L    (GEMM_BASE + 512 + 1024)       // 42496 (OUT=1)
// head staging (OUT=0): xsh 128*132*4=67584 at 0, wsh 20480 at 67584, bl 160
#define XSH_PITCH 132
#define WSH_OFF   67584
#define BLSH_OFF  (WSH_OFF + 20480)
#define SMEM_L0   (BLSH_OFF + 160)               // 88224

#define LDSM_X4(r0,r1,r2,r3,addr) \
    asm volatile("ldmatrix.sync.aligned.m8n8.x4.shared.b16 {%0,%1,%2,%3}, [%4];" \
        : "=r"(r0),"=r"(r1),"=r"(r2),"=r"(r3) : "r"(addr))
#define LDSM_X2(r0,r1,addr) \
    asm volatile("ldmatrix.sync.aligned.m8n8.x2.shared.b16 {%0,%1}, [%2];" \
        : "=r"(r0),"=r"(r1) : "r"(addr))
#define MMA16816(d,a0,a1,a2,a3,b0,b1) \
    asm volatile("mma.sync.aligned.m16n8k16.row.col.f32.bf16.bf16.f32 " \
        "{%0,%1,%2,%3},{%4,%5,%6,%7},{%8,%9},{%0,%1,%2,%3};" \
        : "+f"(d[0]),"+f"(d[1]),"+f"(d[2]),"+f"(d[3]) \
        : "r"(a0),"r"(a1),"r"(a2),"r"(a3),"r"(b0),"r"(b1))

__device__ __forceinline__ unsigned int smem_u32(const void* p) {
    return (unsigned int)__cvta_generic_to_shared(p);
}

// OUT 1: write g_act. OUT 0: write x4out AND compute logits/softmax in-block.
template<int OUT>
__global__ __launch_bounds__(256, 2)
void gemm_norm_kernel(int layer, const float* __restrict__ bias,
                      float2* __restrict__ OUText, int nrows,
                      const float4* __restrict__ Wl4,
                      const float* __restrict__ bl,
                      float* __restrict__ logits,
                      float* __restrict__ probs) {
    extern __shared__ char smem_c[];
    __nv_bfloat16* xhi_s = (__nv_bfloat16*)smem_c;         // [128][PT]
    __nv_bfloat16* xlo_s = xhi_s + 128 * PT;
    __nv_bfloat16* whi_s = xlo_s + 128 * PT;
    __nv_bfloat16* wlo_s = whi_s + 128 * PT;
    float* b_s  = (float*)(smem_c + BS_OFF);               // [128]
    float* ss_s = (float*)(smem_c + SS_OFF);               // [128][2]

    const int tid  = threadIdx.x;
    const int lane = tid & 31;
    const int w    = tid >> 5;
    const int wr   = (w & 3) * 32;
    const int wc   = (w >> 2) * 64;
    const int row0 = blockIdx.x * 128;
    const int woff = layer * (F * F / 8);

    if (tid < 128) b_s[tid] = bias[tid];

    float acc[2][8][4];
    #pragma unroll
    for (int mt = 0; mt < 2; mt++)
        #pragma unroll
        for (int nt = 0; nt < 8; nt++)
            #pragma unroll
            for (int j = 0; j < 4; j++) acc[mt][nt][j] = 0.f;

    const int l15 = lane & 15;
    const int koA = (lane >> 4) << 3;
    const int koB = (l15 >> 3) << 3;

    for (int ks = 0; ks < 4; ks++) {
        // X: load agg fp32 + split hi/lo
        #pragma unroll
        for (int i = tid; i < 1024; i += 256) {
            int r = i >> 3, c = i & 7;
            int gr = row0 + r;
            float4 v = make_float4(0.f, 0.f, 0.f, 0.f);
            if (gr < nrows) v = g_agg[gr * F4 + ks * 8 + c];
            float vals[4] = {v.x, v.y, v.z, v.w};
            __nv_bfloat16 hi[4], lo[4];
            #pragma unroll
            for (int j = 0; j < 4; j++) {
                hi[j] = __float2bfloat16(vals[j]);
                lo[j] = __float2bfloat16(vals[j] - __bfloat162float(hi[j]));
            }
            int off = r * PT + c * 4;
            *(uint2*)(xhi_s + off) = *(uint2*)hi;
            *(uint2*)(xlo_s + off) = *(uint2*)lo;
        }
        // W: copy preconverted bf16
        #pragma unroll
        for (int i = tid; i < 1024; i += 256) {
            int whichW = i >> 9;
            int r = (i >> 2) & 127;
            int c = i & 3;
            int gidx = woff + r * 16 + ks * 4 + c;
            uint4 v = whichW ? ((const uint4*)g_wtlo)[gidx]
                             : ((const uint4*)g_wthi)[gidx];
            __nv_bfloat16* base = whichW ? wlo_s : whi_s;
            *(uint4*)(base + r * PT + c * 8) = v;
        }
        __syncthreads();

        #pragma unroll
        for (int j = 0; j < 2; j++) {
            unsigned int ahi[2][4], alo[2][4];
            #pragma unroll
            for (int mt = 0; mt < 2; mt++) {
                int r = wr + mt * 16 + l15;
                LDSM_X4(ahi[mt][0], ahi[mt][1], ahi[mt][2], ahi[mt][3],
                        smem_u32(xhi_s + r * PT + j * 16 + koA));
                LDSM_X4(alo[mt][0], alo[mt][1], alo[mt][2], alo[mt][3],
                        smem_u32(xlo_s + r * PT + j * 16 + koA));
            }
            #pragma unroll
            for (int nt = 0; nt < 8; nt++) {
                int boff = (wc + nt * 8 + (l15 & 7)) * PT + j * 16 + koB;
                unsigned int bh0, bh1, bl0, bl1;
                LDSM_X2(bh0, bh1, smem_u32(whi_s + boff));
                LDSM_X2(bl0, bl1, smem_u32(wlo_s + boff));
                #pragma unroll
                for (int mt = 0; mt < 2; mt++) {
                    MMA16816(acc[mt][nt], ahi[mt][0], ahi[mt][1], ahi[mt][2], ahi[mt][3], bh0, bh1);
                    MMA16816(acc[mt][nt], ahi[mt][0], ahi[mt][1], ahi[mt][2], ahi[mt][3], bl0, bl1);
                    MMA16816(acc[mt][nt], alo[mt][0], alo[mt][1], alo[mt][2], alo[mt][3], bh0, bh1);
                }
            }
        }
        __syncthreads();
    }

    // ---- epilogue: +bias, L2 norm ----
    const int rA = lane >> 2;
    const int cB = (lane & 3) * 2;
    float ssp[2][2];
    #pragma unroll
    for (int mt = 0; mt < 2; mt++) {
        ssp[mt][0] = 0.f; ssp[mt][1] = 0.f;
        #pragma unroll
        for (int nt = 0; nt < 8; nt++) {
            float b0 = b_s[wc + nt * 8 + cB];
            float b1 = b_s[wc + nt * 8 + cB + 1];
            acc[mt][nt][0] += b0; acc[mt][nt][1] += b1;
            acc[mt][nt][2] += b0; acc[mt][nt][3] += b1;
            ssp[mt][0] += acc[mt][nt][0] * acc[mt][nt][0] + acc[mt][nt][1] * acc[mt][nt][1];
            ssp[mt][1] += acc[mt][nt][2] * acc[mt][nt][2] + acc[mt][nt][3] * acc[mt][nt][3];
        }
        #pragma unroll
        for (int d = 1; d < 4; d <<= 1) {
            ssp[mt][0] += __shfl_xor_sync(0xFFFFFFFFu, ssp[mt][0], d);
            ssp[mt][1] += __shfl_xor_sync(0xFFFFFFFFu, ssp[mt][1], d);
        }
        if ((lane & 3) == 0) {
            ss_s[(wr + mt * 16 + rA) * 2 + (w >> 2)]     = ssp[mt][0];
            ss_s[(wr + mt * 16 + rA + 8) * 2 + (w >> 2)] = ssp[mt][1];
        }
    }
    __syncthreads();

    float invA[2], invB[2];
    #pragma unroll
    for (int mt = 0; mt < 2; mt++) {
        int r0l = wr + mt * 16 + rA;
        float ss0 = ss_s[r0l * 2] + ss_s[r0l * 2 + 1];
        float ss1 = ss_s[(r0l + 8) * 2] + ss_s[(r0l + 8) * 2 + 1];
        invA[mt] = 1.f / fmaxf(sqrtf(ss0), 1e-12f);
        invB[mt] = 1.f / fmaxf(sqrtf(ss1), 1e-12f);
    }
    __syncthreads();   // ss_s fully consumed (xsh staging may overwrite it)

    float* xsh = (float*)smem_c;   // OUT==0 staging, pitch XSH_PITCH
    #pragma unroll
    for (int mt = 0; mt < 2; mt++) {
        int r0l = wr + mt * 16 + rA;
        int gr = row0 + r0l;
        #pragma unroll
        for (int nt = 0; nt < 8; nt++) {
            int c = wc + nt * 8 + cB;
            float2 v0 = make_float2(fmaxf(acc[mt][nt][0] * invA[mt], 0.f),
                                    fmaxf(acc[mt][nt][1] * invA[mt], 0.f));
            float2 v1 = make_float2(fmaxf(acc[mt][nt][2] * invB[mt], 0.f),
                                    fmaxf(acc[mt][nt][3] * invB[mt], 0.f));
            if (OUT) {
                float2* A2 = (float2*)g_act;
                if (gr < nrows)     A2[gr * 64 + (c >> 1)]       = v0;
                if (gr + 8 < nrows) A2[(gr + 8) * 64 + (c >> 1)] = v1;
            } else {
                if (gr < nrows)     OUText[gr * 64 + (c >> 1)]       = v0;
                if (gr + 8 < nrows) OUText[(gr + 8) * 64 + (c >> 1)] = v1;
                *(float2*)(xsh + r0l * XSH_PITCH + c)       = v0;
                *(float2*)(xsh + (r0l + 8) * XSH_PITCH + c) = v1;
            }
        }
    }

    if (OUT == 0) {
        // ---- fused head: logits + softmax for this block's 128 nodes ----
        float4* wsh4 = (float4*)(smem_c + WSH_OFF);   // [128][10] float4
        float*  blsh = (float*)(smem_c + BLSH_OFF);
        for (int i = tid; i < 1280; i += 256) wsh4[i] = Wl4[i];
        if (tid < 40) blsh[tid] = bl[tid];
        __syncthreads();

        int node = tid >> 1;
        int half = tid & 1;
        int gn = row0 + node;

        float lg[20];
        #pragma unroll
        for (int j = 0; j < 20; j++) lg[j] = blsh[half * 20 + j];

        const float4* xrow = (const float4*)(xsh + node * XSH_PITCH);
        #pragma unroll 4
        for (int k4 = 0; k4 < 32; k4++) {
            float4 xv = xrow[k4];
            float xs[4] = {xv.x, xv.y, xv.z, xv.w};
            #pragma unroll
            for (int kk = 0; kk < 4; kk++) {
                int k = k4 * 4 + kk;
                const float4* wrow = wsh4 + k * 10 + half * 5;
                #pragma unroll
                for (int c4 = 0; c4 < 5; c4++) {
                    float4 wv = wrow[c4];
                    lg[c4 * 4 + 0] += xs[kk] * wv.x;
                    lg[c4 * 4 + 1] += xs[kk] * wv.y;
                    lg[c4 * 4 + 2] += xs[kk] * wv.z;
                    lg[c4 * 4 + 3] += xs[kk] * wv.w;
                }
            }
        }

        float m = -1e30f;
        #pragma unroll
        for (int j = 0; j < 20; j++) m = fmaxf(m, lg[j]);
        m = fmaxf(m, __shfl_xor_sync(0xFFFFFFFFu, m, 1));
        float sum = 0.f;
        float ex[20];
        #pragma unroll
        for (int j = 0; j < 20; j++) { ex[j] = expf(lg[j] - m); sum += ex[j]; }
        sum += __shfl_xor_sync(0xFFFFFFFFu, sum, 1);
        float inv = 1.f / sum;

        if (gn < nrows) {
            int base = gn * NCLASS + half * 20;
            #pragma unroll
            for (int j = 0; j < 20; j++) {
                logits[base + j] = lg[j];
                probs[base + j]  = ex[j] * inv;
            }
        }
    }
}

// ---------------- launch ----------------
extern "C" void kernel_launch(void* const* d_in, const int* in_sizes, int n_in,
                              void* d_out, int out_size) {
    const float* x  = (const float*)d_in[0];
    const int*   ei = (const int*)d_in[1];
    const float* W1 = (const float*)d_in[2];
    const float* b1 = (const float*)d_in[3];
    const float* W2 = (const float*)d_in[4];
    const float* b2 = (const float*)d_in[5];
    const float* W3 = (const float*)d_in[6];
    const float* b3 = (const float*)d_in[7];
    const float* W4 = (const float*)d_in[8];
    const float* b4 = (const float*)d_in[9];
    const float* Wl = (const float*)d_in[10];
    const float* bl = (const float*)d_in[11];

    const int* src = ei;
    const int* dst = ei + N_EDGES;

    float* out    = (float*)d_out;
    float* logits = out;
    float* probs  = out + N_NODES * NCLASS;
    float* x4out  = out + 2 * N_NODES * NCLASS;

    const int T = 256;
    const int gemm_blocks = (N_NODES + 127) / 128;
    const int agg_blocks  = (N_NODES * 32 + T - 1) / T;
    const int edge_blocks = (N_EDGES + T - 1) / T;
    const int prep_blocks = (4 * F * F + N_NODES + T - 1) / T;

    cudaFuncSetAttribute(gemm_norm_kernel<1>, cudaFuncAttributeMaxDynamicSharedMemorySize, SMEM_L);
    cudaFuncSetAttribute(gemm_norm_kernel<0>, cudaFuncAttributeMaxDynamicSharedMemorySize, SMEM_L0);

    // prep + CSR
    prep_kernel<<<prep_blocks, T>>>(W1, W2, W3, W4);
    hist_kernel<<<edge_blocks, T>>>(dst);
    scanA_kernel<<<SCAN_BLKS, 1024>>>();
    scanB_kernel<<<1, 64>>>();
    scanC_kernel<<<SCAN_BLKS, 1024>>>();
    fill_kernel<<<edge_blocks, T>>>(src, dst);

    // 4 layers: aggregate-then-GEMM; layer 4 fuses the head
    agg_sum_kernel<0><<<agg_blocks, T>>>((const float4*)x);
    gemm_norm_kernel<1><<<gemm_blocks, T, SMEM_L>>>(0, b1, nullptr, N_NODES, nullptr, nullptr, nullptr, nullptr);
    agg_sum_kernel<1><<<agg_blocks, T>>>(nullptr);
    gemm_norm_kernel<1><<<gemm_blocks, T, SMEM_L>>>(1, b2, nullptr, N_NODES, nullptr, nullptr, nullptr, nullptr);
    agg_sum_kernel<1><<<agg_blocks, T>>>(nullptr);
    gemm_norm_kernel<1><<<gemm_blocks, T, SMEM_L>>>(2, b3, nullptr, N_NODES, nullptr, nullptr, nullptr, nullptr);
    agg_sum_kernel<1><<<agg_blocks, T>>>(nullptr);
    gemm_norm_kernel<0><<<gemm_blocks, T, SMEM_L0>>>(3, b4, (float2*)x4out, N_NODES,
                                                     (const float4*)Wl, bl, logits, probs);
}

// round 13
// speedup vs baseline: 1.4191x; 1.0290x over previous
#include <cuda_runtime.h>
#include <cuda_bf16.h>
#include <cstdint>
#include <math.h>

#define N_NODES 50000
#define N_EDGES 640000
#define F 128
#define F4 32
#define NCLASS 40
#define SCAN_BLKS 49

// ---------------- scratch (static __device__, zero-initialized at load) ----------------
__device__ float4        g_agg[N_NODES * F4];
__device__ float4        g_act[N_NODES * F4];
__device__ __nv_bfloat16 g_wthi[4 * F * F];
__device__ __nv_bfloat16 g_wtlo[4 * F * F];
__device__ int g_cnt[N_NODES];                        // ALWAYS zero at kernel_launch entry
__device__ int g_off[N_NODES + 1];
__device__ int g_cur[N_NODES];
__device__ int g_srcs[N_EDGES];
__device__ unsigned long long g_sstate[SCAN_BLKS];    // ALWAYS zero at entry

// ---------------- hist + W prep (fused; g_cnt pre-zeroed invariant) ----------------
__global__ void hist_prep_kernel(const int* __restrict__ dst,
                                 const float* __restrict__ W1,
                                 const float* __restrict__ W2,
                                 const float* __restrict__ W3,
                                 const float* __restrict__ W4) {
    int i = blockIdx.x * blockDim.x + threadIdx.x;
    if (i < N_EDGES) atomicAdd(&g_cnt[dst[i]], 1);
    int p = i - N_EDGES;
    if (p >= 0 && p < 4 * F * F) {
        int layer = p >> 14;
        int r = p & (F * F - 1);
        int k = r >> 7, n = r & 127;
        const float* W = (layer == 0) ? W1 : (layer == 1) ? W2 : (layer == 2) ? W3 : W4;
        float w = W[k * F + n];
        __nv_bfloat16 h = __float2bfloat16(w);
        g_wthi[layer * F * F + n * F + k] = h;
        g_wtlo[layer * F * F + n * F + k] = __float2bfloat16(w - __bfloat162float(h));
    }
}

// ---------------- single-pass scan (decoupled lookback; 49 blocks co-resident) ----------------
__global__ void scan_kernel() {
    __shared__ int sh[1024];
    __shared__ int sprefix;
    int tid = threadIdx.x;
    int bid = blockIdx.x;
    int i = bid * 1024 + tid;
    int v = (i < N_NODES) ? g_cnt[i] : 0;
    sh[tid] = v;
    __syncthreads();
    for (int off = 1; off < 1024; off <<= 1) {
        int t = (tid >= off) ? sh[tid - off] : 0;
        __syncthreads();
        sh[tid] += t;
        __syncthreads();
    }
    if (tid == 0) {
        int total = sh[1023];
        if (bid == 0) {
            atomicExch(&g_sstate[0], (2ULL << 32) | (unsigned)total);
            sprefix = 0;
        } else {
            atomicExch(&g_sstate[bid], (1ULL << 32) | (unsigned)total);
            int pref = 0;
            for (int j = bid - 1; j >= 0; ) {
                unsigned long long p;
                do { p = atomicAdd(&g_sstate[j], 0ULL); } while ((p >> 32) == 0);
                pref += (int)(p & 0xffffffffULL);
                if ((p >> 32) == 2) break;
                j--;
            }
            sprefix = pref;
            atomicExch(&g_sstate[bid], (2ULL << 32) | (unsigned)(pref + total));
        }
    }
    __syncthreads();
    int excl = sprefix + sh[tid] - v;
    if (i < N_NODES) { g_off[i] = excl; g_cur[i] = excl; }
    if (bid == 0 && tid == 0) g_off[N_NODES] = N_EDGES;
}

// ---------------- fill + restore zero-invariants for next call ----------------
__global__ void fill_kernel(const int* __restrict__ src,
                            const int* __restrict__ dst) {
    int e = blockIdx.x * blockDim.x + threadIdx.x;
    if (e < N_EDGES) {
        int d = dst[e];
        int p = atomicAdd(&g_cur[d], 1);
        g_srcs[p] = src[e];
    }
    if (e < N_NODES) g_cnt[e] = 0;          // consumed by scan; re-zero for next call
    if (e < SCAN_BLKS) g_sstate[e] = 0;     // consumed by scan; re-zero
}

// ---------------- aggregate (pure sum, fp32 gather) ----------------
template<int SEL>
__global__ void agg_sum_kernel(const float4* __restrict__ Xext) {
    int node = (blockIdx.x * blockDim.x + threadIdx.x) >> 5;
    int lane = threadIdx.x & 31;
    if (node >= N_NODES) return;
    int s = g_off[node], e = g_off[node + 1];
    const float4* tab = (SEL == 0) ? Xext : g_act;
    float4 acc = make_float4(0.f, 0.f, 0.f, 0.f);
    int i = s;
    for (; i + 7 < e; i += 8) {
        int u[8];
        #pragma unroll
        for (int j = 0; j < 8; j++) u[j] = __ldg(&g_srcs[i + j]);
        float4 v[8];
        #pragma unroll
        for (int j = 0; j < 8; j++) v[j] = __ldg(&tab[u[j] * F4 + lane]);
        #pragma unroll
        for (int j = 0; j < 8; j++) {
            acc.x += v[j].x; acc.y += v[j].y; acc.z += v[j].z; acc.w += v[j].w;
        }
    }
    for (; i + 1 < e; i += 2) {
        int u0 = __ldg(&g_srcs[i]), u1 = __ldg(&g_srcs[i + 1]);
        float4 v0 = __ldg(&tab[u0 * F4 + lane]);
        float4 v1 = __ldg(&tab[u1 * F4 + lane]);
        acc.x += v0.x + v1.x; acc.y += v0.y + v1.y;
        acc.z += v0.z + v1.z; acc.w += v0.w + v1.w;
    }
    if (i < e) {
        float4 v = __ldg(&tab[__ldg(&g_srcs[i]) * F4 + lane]);
        acc.x += v.x; acc.y += v.y; acc.z += v.z; acc.w += v.w;
    }
    g_agg[node * F4 + lane] = acc;
}

// ---------------- GEMM + bias + L2norm + ReLU (+ fused head), reg-prefetched ----------------
#define PT 40
#define GEMM_BASE (4 * 128 * PT * 2)            // 40960
#define BS_OFF    GEMM_BASE
#define SS_OFF    (GEMM_BASE + 512)
#define SMEM_L    (GEMM_BASE + 512 + 1024)
#define XSH_PITCH 132
#define WSH_OFF   67584
#define BLSH_OFF  (WSH_OFF + 20480)
#define SMEM_L0   (BLSH_OFF + 160)

#define LDSM_X4(r0,r1,r2,r3,addr) \
    asm volatile("ldmatrix.sync.aligned.m8n8.x4.shared.b16 {%0,%1,%2,%3}, [%4];" \
        : "=r"(r0),"=r"(r1),"=r"(r2),"=r"(r3) : "r"(addr))
#define LDSM_X2(r0,r1,addr) \
    asm volatile("ldmatrix.sync.aligned.m8n8.x2.shared.b16 {%0,%1}, [%2];" \
        : "=r"(r0),"=r"(r1) : "r"(addr))
#define MMA16816(d,a0,a1,a2,a3,b0,b1) \
    asm volatile("mma.sync.aligned.m16n8k16.row.col.f32.bf16.bf16.f32 " \
        "{%0,%1,%2,%3},{%4,%5,%6,%7},{%8,%9},{%0,%1,%2,%3};" \
        : "+f"(d[0]),"+f"(d[1]),"+f"(d[2]),"+f"(d[3]) \
        : "r"(a0),"r"(a1),"r"(a2),"r"(a3),"r"(b0),"r"(b1))

__device__ __forceinline__ unsigned int smem_u32(const void* p) {
    return (unsigned int)__cvta_generic_to_shared(p);
}

template<int OUT>
__global__ __launch_bounds__(256, 2)
void gemm_norm_kernel(int layer, const float* __restrict__ bias,
                      float2* __restrict__ OUText, int nrows,
                      const float4* __restrict__ Wl4,
                      const float* __restrict__ bl,
                      float* __restrict__ logits,
                      float* __restrict__ probs) {
    extern __shared__ char smem_c[];
    __nv_bfloat16* xhi_s = (__nv_bfloat16*)smem_c;
    __nv_bfloat16* xlo_s = xhi_s + 128 * PT;
    __nv_bfloat16* whi_s = xlo_s + 128 * PT;
    __nv_bfloat16* wlo_s = whi_s + 128 * PT;
    float* b_s  = (float*)(smem_c + BS_OFF);
    float* ss_s = (float*)(smem_c + SS_OFF);

    const int tid  = threadIdx.x;
    const int lane = tid & 31;
    const int w    = tid >> 5;
    const int wr   = (w & 3) * 32;
    const int wc   = (w >> 2) * 64;
    const int row0 = blockIdx.x * 128;
    const int woff = layer * (F * F / 8);

    if (tid < 128) b_s[tid] = bias[tid];

    float acc[2][8][4];
    #pragma unroll
    for (int mt = 0; mt < 2; mt++)
        #pragma unroll
        for (int nt = 0; nt < 8; nt++)
            #pragma unroll
            for (int j = 0; j < 4; j++) acc[mt][nt][j] = 0.f;

    const int l15 = lane & 15;
    const int koA = (lane >> 4) << 3;
    const int koB = (l15 >> 3) << 3;

    float4 xv[4];
    uint4  wv[4];
    auto load_slab = [&](int ks) {
        #pragma unroll
        for (int t = 0; t < 4; t++) {
            int i = tid + t * 256;
            int r = i >> 3, c = i & 7;
            int gr = row0 + r;
            xv[t] = (gr < nrows) ? __ldg(&g_agg[gr * F4 + ks * 8 + c])
                                 : make_float4(0.f, 0.f, 0.f, 0.f);
        }
        #pragma unroll
        for (int t = 0; t < 4; t++) {
            int i = tid + t * 256;
            int whichW = i >> 9, r = (i >> 2) & 127, c = i & 3;
            int gidx = woff + r * 16 + ks * 4 + c;
            wv[t] = whichW ? ((const uint4*)g_wtlo)[gidx]
                           : ((const uint4*)g_wthi)[gidx];
        }
    };
    auto store_slab = [&]() {
        #pragma unroll
        for (int t = 0; t < 4; t++) {
            int i = tid + t * 256;
            int r = i >> 3, c = i & 7;
            float vals[4] = {xv[t].x, xv[t].y, xv[t].z, xv[t].w};
            __nv_bfloat16 hi[4], lo[4];
            #pragma unroll
            for (int j = 0; j < 4; j++) {
                hi[j] = __float2bfloat16(vals[j]);
                lo[j] = __float2bfloat16(vals[j] - __bfloat162float(hi[j]));
            }
            int off = r * PT + c * 4;
            *(uint2*)(xhi_s + off) = *(uint2*)hi;
            *(uint2*)(xlo_s + off) = *(uint2*)lo;
        }
        #pragma unroll
        for (int t = 0; t < 4; t++) {
            int i = tid + t * 256;
            int whichW = i >> 9, r = (i >> 2) & 127, c = i & 3;
            __nv_bfloat16* base = whichW ? wlo_s : whi_s;
            *(uint4*)(base + r * PT + c * 8) = wv[t];
        }
    };

    load_slab(0);
    for (int ks = 0; ks < 4; ks++) {
        store_slab();
        __syncthreads();
        if (ks < 3) load_slab(ks + 1);

        #pragma unroll
        for (int j = 0; j < 2; j++) {
            unsigned int ahi[2][4], alo[2][4];
            #pragma unroll
            for (int mt = 0; mt < 2; mt++) {
                int r = wr + mt * 16 + l15;
                LDSM_X4(ahi[mt][0], ahi[mt][1], ahi[mt][2], ahi[mt][3],
                        smem_u32(xhi_s + r * PT + j * 16 + koA));
                LDSM_X4(alo[mt][0], alo[mt][1], alo[mt][2], alo[mt][3],
                        smem_u32(xlo_s + r * PT + j * 16 + koA));
            }
            #pragma unroll
            for (int nt = 0; nt < 8; nt++) {
                int boff = (wc + nt * 8 + (l15 & 7)) * PT + j * 16 + koB;
                unsigned int bh0, bh1, bl0, bl1;
                LDSM_X2(bh0, bh1, smem_u32(whi_s + boff));
                LDSM_X2(bl0, bl1, smem_u32(wlo_s + boff));
                #pragma unroll
                for (int mt = 0; mt < 2; mt++) {
                    MMA16816(acc[mt][nt], ahi[mt][0], ahi[mt][1], ahi[mt][2], ahi[mt][3], bh0, bh1);
                    MMA16816(acc[mt][nt], ahi[mt][0], ahi[mt][1], ahi[mt][2], ahi[mt][3], bl0, bl1);
                    MMA16816(acc[mt][nt], alo[mt][0], alo[mt][1], alo[mt][2], alo[mt][3], bh0, bh1);
                }
            }
        }
        __syncthreads();
    }

    // ---- epilogue: +bias, L2 norm ----
    const int rA = lane >> 2;
    const int cB = (lane & 3) * 2;
    float ssp[2][2];
    #pragma unroll
    for (int mt = 0; mt < 2; mt++) {
        ssp[mt][0] = 0.f; ssp[mt][1] = 0.f;
        #pragma unroll
        for (int nt = 0; nt < 8; nt++) {
            float b0 = b_s[wc + nt * 8 + cB];
            float b1 = b_s[wc + nt * 8 + cB + 1];
            acc[mt][nt][0] += b0; acc[mt][nt][1] += b1;
            acc[mt][nt][2] += b0; acc[mt][nt][3] += b1;
            ssp[mt][0] += acc[mt][nt][0] * acc[mt][nt][0] + acc[mt][nt][1] * acc[mt][nt][1];
            ssp[mt][1] += acc[mt][nt][2] * acc[mt][nt][2] + acc[mt][nt][3] * acc[mt][nt][3];
        }
        #pragma unroll
        for (int d = 1; d < 4; d <<= 1) {
            ssp[mt][0] += __shfl_xor_sync(0xFFFFFFFFu, ssp[mt][0], d);
            ssp[mt][1] += __shfl_xor_sync(0xFFFFFFFFu, ssp[mt][1], d);
        }
        if ((lane & 3) == 0) {
            ss_s[(wr + mt * 16 + rA) * 2 + (w >> 2)]     = ssp[mt][0];
            ss_s[(wr + mt * 16 + rA + 8) * 2 + (w >> 2)] = ssp[mt][1];
        }
    }
    __syncthreads();

    float invA[2], invB[2];
    #pragma unroll
    for (int mt = 0; mt < 2; mt++) {
        int r0l = wr + mt * 16 + rA;
        float ss0 = ss_s[r0l * 2] + ss_s[r0l * 2 + 1];
        float ss1 = ss_s[(r0l + 8) * 2] + ss_s[(r0l + 8) * 2 + 1];
        invA[mt] = 1.f / fmaxf(sqrtf(ss0), 1e-12f);
        invB[mt] = 1.f / fmaxf(sqrtf(ss1), 1e-12f);
    }
    __syncthreads();   // ss_s consumed (head staging may overwrite)

    float* xsh = (float*)smem_c;
    #pragma unroll
    for (int mt = 0; mt < 2; mt++) {
        int r0l = wr + mt * 16 + rA;
        int gr = row0 + r0l;
        #pragma unroll
        for (int nt = 0; nt < 8; nt++) {
            int c = wc + nt * 8 + cB;
            float2 v0 = make_float2(fmaxf(acc[mt][nt][0] * invA[mt], 0.f),
                                    fmaxf(acc[mt][nt][1] * invA[mt], 0.f));
            float2 v1 = make_float2(fmaxf(acc[mt][nt][2] * invB[mt], 0.f),
                                    fmaxf(acc[mt][nt][3] * invB[mt], 0.f));
            if (OUT) {
                float2* A2 = (float2*)g_act;
                if (gr < nrows)     A2[gr * 64 + (c >> 1)]       = v0;
                if (gr + 8 < nrows) A2[(gr + 8) * 64 + (c >> 1)] = v1;
            } else {
                if (gr < nrows)     OUText[gr * 64 + (c >> 1)]       = v0;
                if (gr + 8 < nrows) OUText[(gr + 8) * 64 + (c >> 1)] = v1;
                *(float2*)(xsh + r0l * XSH_PITCH + c)       = v0;
                *(float2*)(xsh + (r0l + 8) * XSH_PITCH + c) = v1;
            }
        }
    }

    if (OUT == 0) {
        float4* wsh4 = (float4*)(smem_c + WSH_OFF);
        float*  blsh = (float*)(smem_c + BLSH_OFF);
        for (int i = tid; i < 1280; i += 256) wsh4[i] = Wl4[i];
        if (tid < 40) blsh[tid] = bl[tid];
        __syncthreads();

        int node = tid >> 1;
        int half = tid & 1;
        int gn = row0 + node;

        float lg[20];
        #pragma unroll
        for (int j = 0; j < 20; j++) lg[j] = blsh[half * 20 + j];

        const float4* xrow = (const float4*)(xsh + node * XSH_PITCH);
        #pragma unroll 4
        for (int k4 = 0; k4 < 32; k4++) {
            float4 xvv = xrow[k4];
            float xs[4] = {xvv.x, xvv.y, xvv.z, xvv.w};
            #pragma unroll
            for (int kk = 0; kk < 4; kk++) {
                int k = k4 * 4 + kk;
                const float4* wrow = wsh4 + k * 10 + half * 5;
                #pragma unroll
                for (int c4 = 0; c4 < 5; c4++) {
                    float4 wvv = wrow[c4];
                    lg[c4 * 4 + 0] += xs[kk] * wvv.x;
                    lg[c4 * 4 + 1] += xs[kk] * wvv.y;
                    lg[c4 * 4 + 2] += xs[kk] * wvv.z;
                    lg[c4 * 4 + 3] += xs[kk] * wvv.w;
                }
            }
        }

        float m = -1e30f;
        #pragma unroll
        for (int j = 0; j < 20; j++) m = fmaxf(m, lg[j]);
        m = fmaxf(m, __shfl_xor_sync(0xFFFFFFFFu, m, 1));
        float sum = 0.f;
        float ex[20];
        #pragma unroll
        for (int j = 0; j < 20; j++) { ex[j] = expf(lg[j] - m); sum += ex[j]; }
        sum += __shfl_xor_sync(0xFFFFFFFFu, sum, 1);
        float inv = 1.f / sum;

        if (gn < nrows) {
            int base = gn * NCLASS + half * 20;
            #pragma unroll
            for (int j = 0; j < 20; j++) {
                logits[base + j] = lg[j];
                probs[base + j]  = ex[j] * inv;
            }
        }
    }
}

// ---------------- launch ----------------
extern "C" void kernel_launch(void* const* d_in, const int* in_sizes, int n_in,
                              void* d_out, int out_size) {
    const float* x  = (const float*)d_in[0];
    const int*   ei = (const int*)d_in[1];
    const float* W1 = (const float*)d_in[2];
    const float* b1 = (const float*)d_in[3];
    const float* W2 = (const float*)d_in[4];
    const float* b2 = (const float*)d_in[5];
    const float* W3 = (const float*)d_in[6];
    const float* b3 = (const float*)d_in[7];
    const float* W4 = (const float*)d_in[8];
    const float* b4 = (const float*)d_in[9];
    const float* Wl = (const float*)d_in[10];
    const float* bl = (const float*)d_in[11];

    const int* src = ei;
    const int* dst = ei + N_EDGES;

    float* out    = (float*)d_out;
    float* logits = out;
    float* probs  = out + N_NODES * NCLASS;
    float* x4out  = out + 2 * N_NODES * NCLASS;

    const int T = 256;
    const int gemm_blocks = (N_NODES + 127) / 128;
    const int agg_blocks  = (N_NODES * 32 + T - 1) / T;
    const int hp_blocks   = (N_EDGES + 4 * F * F + T - 1) / T;
    const int edge_blocks = (N_EDGES + T - 1) / T;

    cudaFuncSetAttribute(gemm_norm_kernel<1>, cudaFuncAttributeMaxDynamicSharedMemorySize, SMEM_L);
    cudaFuncSetAttribute(gemm_norm_kernel<0>, cudaFuncAttributeMaxDynamicSharedMemorySize, SMEM_L0);

    // CSR build (g_cnt and g_sstate are zero on entry — static init / re-zeroed by fill)
    hist_prep_kernel<<<hp_blocks, T>>>(dst, W1, W2, W3, W4);
    scan_kernel<<<SCAN_BLKS, 1024>>>();
    fill_kernel<<<edge_blocks, T>>>(src, dst);

    // 4 layers: aggregate-then-GEMM; layer 4 fuses the head
    agg_sum_kernel<0><<<agg_blocks, T>>>((const float4*)x);
    gemm_norm_kernel<1><<<gemm_blocks, T, SMEM_L>>>(0, b1, nullptr, N_NODES, nullptr, nullptr, nullptr, nullptr);
    agg_sum_kernel<1><<<agg_blocks, T>>>(nullptr);
    gemm_norm_kernel<1><<<gemm_blocks, T, SMEM_L>>>(1, b2, nullptr, N_NODES, nullptr, nullptr, nullptr, nullptr);
    agg_sum_kernel<1><<<agg_blocks, T>>>(nullptr);
    gemm_norm_kernel<1><<<gemm_blocks, T, SMEM_L>>>(2, b3, nullptr, N_NODES, nullptr, nullptr, nullptr, nullptr);
    agg_sum_kernel<1><<<agg_blocks, T>>>(nullptr);
    gemm_norm_kernel<0><<<gemm_blocks, T, SMEM_L0>>>(3, b4, (float2*)x4out, N_NODES,
                                                     (const float4*)Wl, bl, logits, probs);
}

// round 14
// speedup vs baseline: 1.5317x; 1.0794x over previous
#include <cuda_runtime.h>
#include <cuda_bf16.h>
#include <cuda_fp16.h>
#include <cstdint>
#include <math.h>

#define N_NODES 50000
#define N_EDGES 640000
#define F 128
#define F4 32
#define NCLASS 40
#define SCAN_BLKS 49

// ---------------- scratch (static __device__, zero-initialized at load) ----------------
__device__ float4        g_agg [N_NODES * F4];   // aggregated sums (fp32)
__device__ __half        g_acth[N_NODES * F];    // activation table (fp16)
__device__ __nv_bfloat16 g_wthi[4 * F * F];
__device__ __nv_bfloat16 g_wtlo[4 * F * F];
__device__ int g_cnt[N_NODES];                   // ALWAYS zero at entry
__device__ int g_off[N_NODES + 1];
__device__ int g_cur[N_NODES];
__device__ int g_srcs[N_EDGES];
__device__ unsigned long long g_sstate[SCAN_BLKS];  // ALWAYS zero at entry

// ---------------- hist + W prep (fused) ----------------
__global__ void hist_prep_kernel(const int* __restrict__ dst,
                                 const float* __restrict__ W1,
                                 const float* __restrict__ W2,
                                 const float* __restrict__ W3,
                                 const float* __restrict__ W4) {
    int i = blockIdx.x * blockDim.x + threadIdx.x;
    if (i < N_EDGES) atomicAdd(&g_cnt[dst[i]], 1);
    int p = i - N_EDGES;
    if (p >= 0 && p < 4 * F * F) {
        int layer = p >> 14;
        int r = p & (F * F - 1);
        int k = r >> 7, n = r & 127;
        const float* W = (layer == 0) ? W1 : (layer == 1) ? W2 : (layer == 2) ? W3 : W4;
        float w = W[k * F + n];
        __nv_bfloat16 h = __float2bfloat16(w);
        g_wthi[layer * F * F + n * F + k] = h;
        g_wtlo[layer * F * F + n * F + k] = __float2bfloat16(w - __bfloat162float(h));
    }
}

// ---------------- single-pass scan (decoupled lookback) ----------------
__global__ void scan_kernel() {
    __shared__ int sh[1024];
    __shared__ int sprefix;
    int tid = threadIdx.x;
    int bid = blockIdx.x;
    int i = bid * 1024 + tid;
    int v = (i < N_NODES) ? g_cnt[i] : 0;
    sh[tid] = v;
    __syncthreads();
    for (int off = 1; off < 1024; off <<= 1) {
        int t = (tid >= off) ? sh[tid - off] : 0;
        __syncthreads();
        sh[tid] += t;
        __syncthreads();
    }
    if (tid == 0) {
        int total = sh[1023];
        if (bid == 0) {
            atomicExch(&g_sstate[0], (2ULL << 32) | (unsigned)total);
            sprefix = 0;
        } else {
            atomicExch(&g_sstate[bid], (1ULL << 32) | (unsigned)total);
            int pref = 0;
            for (int j = bid - 1; j >= 0; ) {
                unsigned long long p;
                do { p = atomicAdd(&g_sstate[j], 0ULL); } while ((p >> 32) == 0);
                pref += (int)(p & 0xffffffffULL);
                if ((p >> 32) == 2) break;
                j--;
            }
            sprefix = pref;
            atomicExch(&g_sstate[bid], (2ULL << 32) | (unsigned)(pref + total));
        }
    }
    __syncthreads();
    int excl = sprefix + sh[tid] - v;
    if (i < N_NODES) { g_off[i] = excl; g_cur[i] = excl; }
    if (bid == 0 && tid == 0) g_off[N_NODES] = N_EDGES;
}

// ---------------- fill + restore zero-invariants ----------------
__global__ void fill_kernel(const int* __restrict__ src,
                            const int* __restrict__ dst) {
    int e = blockIdx.x * blockDim.x + threadIdx.x;
    if (e < N_EDGES) {
        int d = dst[e];
        int p = atomicAdd(&g_cur[d], 1);
        g_srcs[p] = src[e];
    }
    if (e < N_NODES) g_cnt[e] = 0;
    if (e < SCAN_BLKS) g_sstate[e] = 0;
}

// ---------------- aggregate (SEL 0: fp32 external x; SEL 1: fp16 g_acth) ----------------
template<int SEL>
__global__ void agg_sum_kernel(const float4* __restrict__ Xext) {
    int node = (blockIdx.x * blockDim.x + threadIdx.x) >> 5;
    int lane = threadIdx.x & 31;
    if (node >= N_NODES) return;
    int s = g_off[node], e = g_off[node + 1];
    float4 acc = make_float4(0.f, 0.f, 0.f, 0.f);
    int i = s;
    if (SEL == 0) {
        for (; i + 7 < e; i += 8) {
            int u[8];
            #pragma unroll
            for (int j = 0; j < 8; j++) u[j] = __ldg(&g_srcs[i + j]);
            float4 v[8];
            #pragma unroll
            for (int j = 0; j < 8; j++) v[j] = __ldg(&Xext[u[j] * F4 + lane]);
            #pragma unroll
            for (int j = 0; j < 8; j++) {
                acc.x += v[j].x; acc.y += v[j].y; acc.z += v[j].z; acc.w += v[j].w;
            }
        }
        for (; i < e; i++) {
            float4 v = __ldg(&Xext[__ldg(&g_srcs[i]) * F4 + lane]);
            acc.x += v.x; acc.y += v.y; acc.z += v.z; acc.w += v.w;
        }
    } else {
        const uint2* tabh = (const uint2*)g_acth;   // 32 uint2 per row
        for (; i + 7 < e; i += 8) {
            int u[8];
            #pragma unroll
            for (int j = 0; j < 8; j++) u[j] = __ldg(&g_srcs[i + j]);
            uint2 rv[8];
            #pragma unroll
            for (int j = 0; j < 8; j++) rv[j] = __ldg(&tabh[u[j] * 32 + lane]);
            #pragma unroll
            for (int j = 0; j < 8; j++) {
                float2 f0 = __half22float2(*(__half2*)&rv[j].x);
                float2 f1 = __half22float2(*(__half2*)&rv[j].y);
                acc.x += f0.x; acc.y += f0.y; acc.z += f1.x; acc.w += f1.y;
            }
        }
        for (; i < e; i++) {
            uint2 rv = __ldg(&tabh[__ldg(&g_srcs[i]) * 32 + lane]);
            float2 f0 = __half22float2(*(__half2*)&rv.x);
            float2 f1 = __half22float2(*(__half2*)&rv.y);
            acc.x += f0.x; acc.y += f0.y; acc.z += f1.x; acc.w += f1.y;
        }
    }
    g_agg[node * F4 + lane] = acc;
}

// ---------------- GEMM + bias + L2norm + ReLU (+ fused head), reg-prefetched ----------------
#define PT 40
#define GEMM_BASE (4 * 128 * PT * 2)
#define BS_OFF    GEMM_BASE
#define SS_OFF    (GEMM_BASE + 512)
#define SMEM_L    (GEMM_BASE + 512 + 1024)
#define XSH_PITCH 132
#define WSH_OFF   67584
#define BLSH_OFF  (WSH_OFF + 20480)
#define SMEM_L0   (BLSH_OFF + 160)

#define LDSM_X4(r0,r1,r2,r3,addr) \
    asm volatile("ldmatrix.sync.aligned.m8n8.x4.shared.b16 {%0,%1,%2,%3}, [%4];" \
        : "=r"(r0),"=r"(r1),"=r"(r2),"=r"(r3) : "r"(addr))
#define LDSM_X2(r0,r1,addr) \
    asm volatile("ldmatrix.sync.aligned.m8n8.x2.shared.b16 {%0,%1}, [%2];" \
        : "=r"(r0),"=r"(r1) : "r"(addr))
#define MMA16816(d,a0,a1,a2,a3,b0,b1) \
    asm volatile("mma.sync.aligned.m16n8k16.row.col.f32.bf16.bf16.f32 " \
        "{%0,%1,%2,%3},{%4,%5,%6,%7},{%8,%9},{%0,%1,%2,%3};" \
        : "+f"(d[0]),"+f"(d[1]),"+f"(d[2]),"+f"(d[3]) \
        : "r"(a0),"r"(a1),"r"(a2),"r"(a3),"r"(b0),"r"(b1))

__device__ __forceinline__ unsigned int smem_u32(const void* p) {
    return (unsigned int)__cvta_generic_to_shared(p);
}

template<int OUT>
__global__ __launch_bounds__(256, 2)
void gemm_norm_kernel(int layer, const float* __restrict__ bias,
                      float2* __restrict__ OUText, int nrows,
                      const float4* __restrict__ Wl4,
                      const float* __restrict__ bl,
                      float* __restrict__ logits,
                      float* __restrict__ probs) {
    extern __shared__ char smem_c[];
    __nv_bfloat16* xhi_s = (__nv_bfloat16*)smem_c;
    __nv_bfloat16* xlo_s = xhi_s + 128 * PT;
    __nv_bfloat16* whi_s = xlo_s + 128 * PT;
    __nv_bfloat16* wlo_s = whi_s + 128 * PT;
    float* b_s  = (float*)(smem_c + BS_OFF);
    float* ss_s = (float*)(smem_c + SS_OFF);

    const int tid  = threadIdx.x;
    const int lane = tid & 31;
    const int w    = tid >> 5;
    const int wr   = (w & 3) * 32;
    const int wc   = (w >> 2) * 64;
    const int row0 = blockIdx.x * 128;
    const int woff = layer * (F * F / 8);

    if (tid < 128) b_s[tid] = bias[tid];

    float acc[2][8][4];
    #pragma unroll
    for (int mt = 0; mt < 2; mt++)
        #pragma unroll
        for (int nt = 0; nt < 8; nt++)
            #pragma unroll
            for (int j = 0; j < 4; j++) acc[mt][nt][j] = 0.f;

    const int l15 = lane & 15;
    const int koA = (lane >> 4) << 3;
    const int koB = (l15 >> 3) << 3;

    float4 xv[4];
    uint4  wv[4];
    auto load_slab = [&](int ks) {
        #pragma unroll
        for (int t = 0; t < 4; t++) {
            int i = tid + t * 256;
            int r = i >> 3, c = i & 7;
            int gr = row0 + r;
            xv[t] = (gr < nrows) ? __ldg(&g_agg[gr * F4 + ks * 8 + c])
                                 : make_float4(0.f, 0.f, 0.f, 0.f);
        }
        #pragma unroll
        for (int t = 0; t < 4; t++) {
            int i = tid + t * 256;
            int whichW = i >> 9, r = (i >> 2) & 127, c = i & 3;
            int gidx = woff + r * 16 + ks * 4 + c;
            wv[t] = whichW ? ((const uint4*)g_wtlo)[gidx]
                           : ((const uint4*)g_wthi)[gidx];
        }
    };
    auto store_slab = [&]() {
        #pragma unroll
        for (int t = 0; t < 4; t++) {
            int i = tid + t * 256;
            int r = i >> 3, c = i & 7;
            float vals[4] = {xv[t].x, xv[t].y, xv[t].z, xv[t].w};
            __nv_bfloat16 hi[4], lo[4];
            #pragma unroll
            for (int j = 0; j < 4; j++) {
                hi[j] = __float2bfloat16(vals[j]);
                lo[j] = __float2bfloat16(vals[j] - __bfloat162float(hi[j]));
            }
            int off = r * PT + c * 4;
            *(uint2*)(xhi_s + off) = *(uint2*)hi;
            *(uint2*)(xlo_s + off) = *(uint2*)lo;
        }
        #pragma unroll
        for (int t = 0; t < 4; t++) {
            int i = tid + t * 256;
            int whichW = i >> 9, r = (i >> 2) & 127, c = i & 3;
            __nv_bfloat16* base = whichW ? wlo_s : whi_s;
            *(uint4*)(base + r * PT + c * 8) = wv[t];
        }
    };

    load_slab(0);
    for (int ks = 0; ks < 4; ks++) {
        store_slab();
        __syncthreads();
        if (ks < 3) load_slab(ks + 1);

        #pragma unroll
        for (int j = 0; j < 2; j++) {
            unsigned int ahi[2][4], alo[2][4];
            #pragma unroll
            for (int mt = 0; mt < 2; mt++) {
                int r = wr + mt * 16 + l15;
                LDSM_X4(ahi[mt][0], ahi[mt][1], ahi[mt][2], ahi[mt][3],
                        smem_u32(xhi_s + r * PT + j * 16 + koA));
                LDSM_X4(alo[mt][0], alo[mt][1], alo[mt][2], alo[mt][3],
                        smem_u32(xlo_s + r * PT + j * 16 + koA));
            }
            #pragma unroll
            for (int nt = 0; nt < 8; nt++) {
                int boff = (wc + nt * 8 + (l15 & 7)) * PT + j * 16 + koB;
                unsigned int bh0, bh1, bl0, bl1;
                LDSM_X2(bh0, bh1, smem_u32(whi_s + boff));
                LDSM_X2(bl0, bl1, smem_u32(wlo_s + boff));
                #pragma unroll
                for (int mt = 0; mt < 2; mt++) {
                    MMA16816(acc[mt][nt], ahi[mt][0], ahi[mt][1], ahi[mt][2], ahi[mt][3], bh0, bh1);
                    MMA16816(acc[mt][nt], ahi[mt][0], ahi[mt][1], ahi[mt][2], ahi[mt][3], bl0, bl1);
                    MMA16816(acc[mt][nt], alo[mt][0], alo[mt][1], alo[mt][2], alo[mt][3], bh0, bh1);
                }
            }
        }
        __syncthreads();
    }

    // ---- epilogue: +bias, L2 norm ----
    const int rA = lane >> 2;
    const int cB = (lane & 3) * 2;
    float ssp[2][2];
    #pragma unroll
    for (int mt = 0; mt < 2; mt++) {
        ssp[mt][0] = 0.f; ssp[mt][1] = 0.f;
        #pragma unroll
        for (int nt = 0; nt < 8; nt++) {
            float b0 = b_s[wc + nt * 8 + cB];
            float b1 = b_s[wc + nt * 8 + cB + 1];
            acc[mt][nt][0] += b0; acc[mt][nt][1] += b1;
            acc[mt][nt][2] += b0; acc[mt][nt][3] += b1;
            ssp[mt][0] += acc[mt][nt][0] * acc[mt][nt][0] + acc[mt][nt][1] * acc[mt][nt][1];
            ssp[mt][1] += acc[mt][nt][2] * acc[mt][nt][2] + acc[mt][nt][3] * acc[mt][nt][3];
        }
        #pragma unroll
        for (int d = 1; d < 4; d <<= 1) {
            ssp[mt][0] += __shfl_xor_sync(0xFFFFFFFFu, ssp[mt][0], d);
            ssp[mt][1] += __shfl_xor_sync(0xFFFFFFFFu, ssp[mt][1], d);
        }
        if ((lane & 3) == 0) {
            ss_s[(wr + mt * 16 + rA) * 2 + (w >> 2)]     = ssp[mt][0];
            ss_s[(wr + mt * 16 + rA + 8) * 2 + (w >> 2)] = ssp[mt][1];
        }
    }
    __syncthreads();

    float invA[2], invB[2];
    #pragma unroll
    for (int mt = 0; mt < 2; mt++) {
        int r0l = wr + mt * 16 + rA;
        float ss0 = ss_s[r0l * 2] + ss_s[r0l * 2 + 1];
        float ss1 = ss_s[(r0l + 8) * 2] + ss_s[(r0l + 8) * 2 + 1];
        invA[mt] = 1.f / fmaxf(sqrtf(ss0), 1e-12f);
        invB[mt] = 1.f / fmaxf(sqrtf(ss1), 1e-12f);
    }
    __syncthreads();

    float* xsh = (float*)smem_c;
    #pragma unroll
    for (int mt = 0; mt < 2; mt++) {
        int r0l = wr + mt * 16 + rA;
        int gr = row0 + r0l;
        #pragma unroll
        for (int nt = 0; nt < 8; nt++) {
            int c = wc + nt * 8 + cB;
            float2 v0 = make_float2(fmaxf(acc[mt][nt][0] * invA[mt], 0.f),
                                    fmaxf(acc[mt][nt][1] * invA[mt], 0.f));
            float2 v1 = make_float2(fmaxf(acc[mt][nt][2] * invB[mt], 0.f),
                                    fmaxf(acc[mt][nt][3] * invB[mt], 0.f));
            if (OUT) {
                __half2* A2h = (__half2*)g_acth;   // 64 half2 per row
                if (gr < nrows)     A2h[gr * 64 + (c >> 1)]       = __floats2half2_rn(v0.x, v0.y);
                if (gr + 8 < nrows) A2h[(gr + 8) * 64 + (c >> 1)] = __floats2half2_rn(v1.x, v1.y);
            } else {
                if (gr < nrows)     OUText[gr * 64 + (c >> 1)]       = v0;
                if (gr + 8 < nrows) OUText[(gr + 8) * 64 + (c >> 1)] = v1;
                *(float2*)(xsh + r0l * XSH_PITCH + c)       = v0;
                *(float2*)(xsh + (r0l + 8) * XSH_PITCH + c) = v1;
            }
        }
    }

    if (OUT == 0) {
        float4* wsh4 = (float4*)(smem_c + WSH_OFF);
        float*  blsh = (float*)(smem_c + BLSH_OFF);
        for (int i = tid; i < 1280; i += 256) wsh4[i] = Wl4[i];
        if (tid < 40) blsh[tid] = bl[tid];
        __syncthreads();

        int node = tid >> 1;
        int half = tid & 1;
        int gn = row0 + node;

        float lg[20];
        #pragma unroll
        for (int j = 0; j < 20; j++) lg[j] = blsh[half * 20 + j];

        const float4* xrow = (const float4*)(xsh + node * XSH_PITCH);
        #pragma unroll 4
        for (int k4 = 0; k4 < 32; k4++) {
            float4 xvv = xrow[k4];
            float xs[4] = {xvv.x, xvv.y, xvv.z, xvv.w};
            #pragma unroll
            for (int kk = 0; kk < 4; kk++) {
                int k = k4 * 4 + kk;
                const float4* wrow = wsh4 + k * 10 + half * 5;
                #pragma unroll
                for (int c4 = 0; c4 < 5; c4++) {
                    float4 wvv = wrow[c4];
                    lg[c4 * 4 + 0] += xs[kk] * wvv.x;
                    lg[c4 * 4 + 1] += xs[kk] * wvv.y;
                    lg[c4 * 4 + 2] += xs[kk] * wvv.z;
                    lg[c4 * 4 + 3] += xs[kk] * wvv.w;
                }
            }
        }

        float m = -1e30f;
        #pragma unroll
        for (int j = 0; j < 20; j++) m = fmaxf(m, lg[j]);
        m = fmaxf(m, __shfl_xor_sync(0xFFFFFFFFu, m, 1));
        float sum = 0.f;
        float ex[20];
        #pragma unroll
        for (int j = 0; j < 20; j++) { ex[j] = expf(lg[j] - m); sum += ex[j]; }
        sum += __shfl_xor_sync(0xFFFFFFFFu, sum, 1);
        float inv = 1.f / sum;

        if (gn < nrows) {
            int base = gn * NCLASS + half * 20;
            #pragma unroll
            for (int j = 0; j < 20; j++) {
                logits[base + j] = lg[j];
                probs[base + j]  = ex[j] * inv;
            }
        }
    }
}

// ---------------- launch ----------------
extern "C" void kernel_launch(void* const* d_in, const int* in_sizes, int n_in,
                              void* d_out, int out_size) {
    const float* x  = (const float*)d_in[0];
    const int*   ei = (const int*)d_in[1];
    const float* W1 = (const float*)d_in[2];
    const float* b1 = (const float*)d_in[3];
    const float* W2 = (const float*)d_in[4];
    const float* b2 = (const float*)d_in[5];
    const float* W3 = (const float*)d_in[6];
    const float* b3 = (const float*)d_in[7];
    const float* W4 = (const float*)d_in[8];
    const float* b4 = (const float*)d_in[9];
    const float* Wl = (const float*)d_in[10];
    const float* bl = (const float*)d_in[11];

    const int* src = ei;
    const int* dst = ei + N_EDGES;

    float* out    = (float*)d_out;
    float* logits = out;
    float* probs  = out + N_NODES * NCLASS;
    float* x4out  = out + 2 * N_NODES * NCLASS;

    const int T = 256;
    const int gemm_blocks = (N_NODES + 127) / 128;
    const int agg_blocks  = (N_NODES * 32 + T - 1) / T;
    const int hp_blocks   = (N_EDGES + 4 * F * F + T - 1) / T;
    const int edge_blocks = (N_EDGES + T - 1) / T;

    cudaFuncSetAttribute(gemm_norm_kernel<1>, cudaFuncAttributeMaxDynamicSharedMemorySize, SMEM_L);
    cudaFuncSetAttribute(gemm_norm_kernel<0>, cudaFuncAttributeMaxDynamicSharedMemorySize, SMEM_L0);

    // CSR build
    hist_prep_kernel<<<hp_blocks, T>>>(dst, W1, W2, W3, W4);
    scan_kernel<<<SCAN_BLKS, 1024>>>();
    fill_kernel<<<edge_blocks, T>>>(src, dst);

    // 4 layers: aggregate-then-GEMM; fp16 table for layers 2-4; layer 4 fuses head
    agg_sum_kernel<0><<<agg_blocks, T>>>((const float4*)x);
    gemm_norm_kernel<1><<<gemm_blocks, T, SMEM_L>>>(0, b1, nullptr, N_NODES, nullptr, nullptr, nullptr, nullptr);
    agg_sum_kernel<1><<<agg_blocks, T>>>(nullptr);
    gemm_norm_kernel<1><<<gemm_blocks, T, SMEM_L>>>(1, b2, nullptr, N_NODES, nullptr, nullptr, nullptr, nullptr);
    agg_sum_kernel<1><<<agg_blocks, T>>>(nullptr);
    gemm_norm_kernel<1><<<gemm_blocks, T, SMEM_L>>>(2, b3, nullptr, N_NODES, nullptr, nullptr, nullptr, nullptr);
    agg_sum_kernel<1><<<agg_blocks, T>>>(nullptr);
    gemm_norm_kernel<0><<<gemm_blocks, T, SMEM_L0>>>(3, b4, (float2*)x4out, N_NODES,
                                                     (const float4*)Wl, bl, logits, probs);
}

// round 15
// speedup vs baseline: 1.5594x; 1.0181x over previous
#include <cuda_runtime.h>
#include <cuda_bf16.h>
#include <cuda_fp16.h>
#include <cstdint>
#include <math.h>

#define N_NODES 50000
#define N_EDGES 640000
#define F 128
#define F4 32
#define NCLASS 40
#define SCAN_BLKS 49

// ---------------- scratch (static __device__, zero-initialized at load) ----------------
__device__ float4        g_agg [N_NODES * F4];   // aggregated sums (fp32)
__device__ __half        g_xh  [N_NODES * F];    // external x as fp16
__device__ __half        g_acth[N_NODES * F];    // activation table (fp16)
__device__ __nv_bfloat16 g_wthi[4 * F * F];
__device__ __nv_bfloat16 g_wtlo[4 * F * F];
__device__ int g_cnt[N_NODES];                   // ALWAYS zero at entry
__device__ int g_off[N_NODES + 1];
__device__ int g_cur[N_NODES];
__device__ int g_srcs[N_EDGES];
__device__ unsigned long long g_sstate[SCAN_BLKS];  // ALWAYS zero at entry

// ---------------- hist + W prep + x->fp16 convert (fused) ----------------
__global__ void hist_prep_kernel(const int* __restrict__ dst,
                                 const float* __restrict__ W1,
                                 const float* __restrict__ W2,
                                 const float* __restrict__ W3,
                                 const float* __restrict__ W4,
                                 const float4* __restrict__ X4) {
    int i = blockIdx.x * blockDim.x + threadIdx.x;
    if (i < N_EDGES) atomicAdd(&g_cnt[dst[i]], 1);
    int p = i - N_EDGES;
    if (p >= 0 && p < 4 * F * F) {
        int layer = p >> 14;
        int r = p & (F * F - 1);
        int k = r >> 7, n = r & 127;
        const float* W = (layer == 0) ? W1 : (layer == 1) ? W2 : (layer == 2) ? W3 : W4;
        float w = W[k * F + n];
        __nv_bfloat16 h = __float2bfloat16(w);
        g_wthi[layer * F * F + n * F + k] = h;
        g_wtlo[layer * F * F + n * F + k] = __float2bfloat16(w - __bfloat162float(h));
    }
    int q = i - N_EDGES - 4 * F * F;
    if (q >= 0 && q < N_NODES * F4) {
        float4 v = __ldg(&X4[q]);
        uint2 hv;
        *(__half2*)&hv.x = __floats2half2_rn(v.x, v.y);
        *(__half2*)&hv.y = __floats2half2_rn(v.z, v.w);
        ((uint2*)g_xh)[q] = hv;
    }
}

// ---------------- single-pass scan (decoupled lookback) ----------------
__global__ void scan_kernel() {
    __shared__ int sh[1024];
    __shared__ int sprefix;
    int tid = threadIdx.x;
    int bid = blockIdx.x;
    int i = bid * 1024 + tid;
    int v = (i < N_NODES) ? g_cnt[i] : 0;
    sh[tid] = v;
    __syncthreads();
    for (int off = 1; off < 1024; off <<= 1) {
        int t = (tid >= off) ? sh[tid - off] : 0;
        __syncthreads();
        sh[tid] += t;
        __syncthreads();
    }
    if (tid == 0) {
        int total = sh[1023];
        if (bid == 0) {
            atomicExch(&g_sstate[0], (2ULL << 32) | (unsigned)total);
            sprefix = 0;
        } else {
            atomicExch(&g_sstate[bid], (1ULL << 32) | (unsigned)total);
            int pref = 0;
            for (int j = bid - 1; j >= 0; ) {
                unsigned long long p;
                do { p = atomicAdd(&g_sstate[j], 0ULL); } while ((p >> 32) == 0);
                pref += (int)(p & 0xffffffffULL);
                if ((p >> 32) == 2) break;
                j--;
            }
            sprefix = pref;
            atomicExch(&g_sstate[bid], (2ULL << 32) | (unsigned)(pref + total));
        }
    }
    __syncthreads();
    int excl = sprefix + sh[tid] - v;
    if (i < N_NODES) { g_off[i] = excl; g_cur[i] = excl; }
    if (bid == 0 && tid == 0) g_off[N_NODES] = N_EDGES;
}

// ---------------- fill + restore zero-invariants ----------------
__global__ void fill_kernel(const int* __restrict__ src,
                            const int* __restrict__ dst) {
    int e = blockIdx.x * blockDim.x + threadIdx.x;
    if (e < N_EDGES) {
        int d = dst[e];
        int p = atomicAdd(&g_cur[d], 1);
        g_srcs[p] = src[e];
    }
    if (e < N_NODES) g_cnt[e] = 0;
    if (e < SCAN_BLKS) g_sstate[e] = 0;
}

// ---------------- aggregate (fp16 gather; SEL 0: g_xh, SEL 1: g_acth) ----------------
template<int SEL>
__global__ void agg_sum_kernel() {
    int node = (blockIdx.x * blockDim.x + threadIdx.x) >> 5;
    int lane = threadIdx.x & 31;
    if (node >= N_NODES) return;
    int s = g_off[node], e = g_off[node + 1];
    const uint2* tabh = (const uint2*)(SEL == 0 ? g_xh : g_acth);   // 32 uint2/row
    float4 acc = make_float4(0.f, 0.f, 0.f, 0.f);
    int i = s;
    for (; i + 7 < e; i += 8) {
        int u[8];
        #pragma unroll
        for (int j = 0; j < 8; j++) u[j] = __ldg(&g_srcs[i + j]);
        uint2 rv[8];
        #pragma unroll
        for (int j = 0; j < 8; j++) rv[j] = __ldg(&tabh[u[j] * 32 + lane]);
        #pragma unroll
        for (int j = 0; j < 8; j++) {
            float2 f0 = __half22float2(*(__half2*)&rv[j].x);
            float2 f1 = __half22float2(*(__half2*)&rv[j].y);
            acc.x += f0.x; acc.y += f0.y; acc.z += f1.x; acc.w += f1.y;
        }
    }
    for (; i < e; i++) {
        uint2 rv = __ldg(&tabh[__ldg(&g_srcs[i]) * 32 + lane]);
        float2 f0 = __half22float2(*(__half2*)&rv.x);
        float2 f1 = __half22float2(*(__half2*)&rv.y);
        acc.x += f0.x; acc.y += f0.y; acc.z += f1.x; acc.w += f1.y;
    }
    g_agg[node * F4 + lane] = acc;
}

// ---------------- GEMM + bias + L2norm + ReLU (+ fused head), reg-prefetched ----------------
#define PT 40
#define GEMM_BASE (4 * 128 * PT * 2)
#define BS_OFF    GEMM_BASE
#define SS_OFF    (GEMM_BASE + 512)
#define SMEM_L    (GEMM_BASE + 512 + 1024)
#define XSH_PITCH 132
#define WSH_OFF   67584
#define BLSH_OFF  (WSH_OFF + 20480)
#define SMEM_L0   (BLSH_OFF + 160)

#define LDSM_X4(r0,r1,r2,r3,addr) \
    asm volatile("ldmatrix.sync.aligned.m8n8.x4.shared.b16 {%0,%1,%2,%3}, [%4];" \
        : "=r"(r0),"=r"(r1),"=r"(r2),"=r"(r3) : "r"(addr))
#define LDSM_X2(r0,r1,addr) \
    asm volatile("ldmatrix.sync.aligned.m8n8.x2.shared.b16 {%0,%1}, [%2];" \
        : "=r"(r0),"=r"(r1) : "r"(addr))
#define MMA16816(d,a0,a1,a2,a3,b0,b1) \
    asm volatile("mma.sync.aligned.m16n8k16.row.col.f32.bf16.bf16.f32 " \
        "{%0,%1,%2,%3},{%4,%5,%6,%7},{%8,%9},{%0,%1,%2,%3};" \
        : "+f"(d[0]),"+f"(d[1]),"+f"(d[2]),"+f"(d[3]) \
        : "r"(a0),"r"(a1),"r"(a2),"r"(a3),"r"(b0),"r"(b1))

__device__ __forceinline__ unsigned int smem_u32(const void* p) {
    return (unsigned int)__cvta_generic_to_shared(p);
}

template<int OUT>
__global__ __launch_bounds__(256, 2)
void gemm_norm_kernel(int layer, const float* __restrict__ bias,
                      float2* __restrict__ OUText, int nrows,
                      const float4* __restrict__ Wl4,
                      const float* __restrict__ bl,
                      float* __restrict__ logits,
                      float* __restrict__ probs) {
    extern __shared__ char smem_c[];
    __nv_bfloat16* xhi_s = (__nv_bfloat16*)smem_c;
    __nv_bfloat16* xlo_s = xhi_s + 128 * PT;
    __nv_bfloat16* whi_s = xlo_s + 128 * PT;
    __nv_bfloat16* wlo_s = whi_s + 128 * PT;
    float* b_s  = (float*)(smem_c + BS_OFF);
    float* ss_s = (float*)(smem_c + SS_OFF);

    const int tid  = threadIdx.x;
    const int lane = tid & 31;
    const int w    = tid >> 5;
    const int wr   = (w & 3) * 32;
    const int wc   = (w >> 2) * 64;
    const int row0 = blockIdx.x * 128;
    const int woff = layer * (F * F / 8);

    if (tid < 128) b_s[tid] = bias[tid];

    float acc[2][8][4];
    #pragma unroll
    for (int mt = 0; mt < 2; mt++)
        #pragma unroll
        for (int nt = 0; nt < 8; nt++)
            #pragma unroll
            for (int j = 0; j < 4; j++) acc[mt][nt][j] = 0.f;

    const int l15 = lane & 15;
    const int koA = (lane >> 4) << 3;
    const int koB = (l15 >> 3) << 3;

    float4 xv[4];
    uint4  wv[4];
    auto load_slab = [&](int ks) {
        #pragma unroll
        for (int t = 0; t < 4; t++) {
            int i = tid + t * 256;
            int r = i >> 3, c = i & 7;
            int gr = row0 + r;
            xv[t] = (gr < nrows) ? __ldg(&g_agg[gr * F4 + ks * 8 + c])
                                 : make_float4(0.f, 0.f, 0.f, 0.f);
        }
        #pragma unroll
        for (int t = 0; t < 4; t++) {
            int i = tid + t * 256;
            int whichW = i >> 9, r = (i >> 2) & 127, c = i & 3;
            int gidx = woff + r * 16 + ks * 4 + c;
            wv[t] = whichW ? ((const uint4*)g_wtlo)[gidx]
                           : ((const uint4*)g_wthi)[gidx];
        }
    };
    auto store_slab = [&]() {
        #pragma unroll
        for (int t = 0; t < 4; t++) {
            int i = tid + t * 256;
            int r = i >> 3, c = i & 7;
            float vals[4] = {xv[t].x, xv[t].y, xv[t].z, xv[t].w};
            __nv_bfloat16 hi[4], lo[4];
            #pragma unroll
            for (int j = 0; j < 4; j++) {
                hi[j] = __float2bfloat16(vals[j]);
                lo[j] = __float2bfloat16(vals[j] - __bfloat162float(hi[j]));
            }
            int off = r * PT + c * 4;
            *(uint2*)(xhi_s + off) = *(uint2*)hi;
            *(uint2*)(xlo_s + off) = *(uint2*)lo;
        }
        #pragma unroll
        for (int t = 0; t < 4; t++) {
            int i = tid + t * 256;
            int whichW = i >> 9, r = (i >> 2) & 127, c = i & 3;
            __nv_bfloat16* base = whichW ? wlo_s : whi_s;
            *(uint4*)(base + r * PT + c * 8) = wv[t];
        }
    };

    load_slab(0);
    for (int ks = 0; ks < 4; ks++) {
        store_slab();
        __syncthreads();
        if (ks < 3) load_slab(ks + 1);

        #pragma unroll
        for (int j = 0; j < 2; j++) {
            unsigned int ahi[2][4], alo[2][4];
            #pragma unroll
            for (int mt = 0; mt < 2; mt++) {
                int r = wr + mt * 16 + l15;
                LDSM_X4(ahi[mt][0], ahi[mt][1], ahi[mt][2], ahi[mt][3],
                        smem_u32(xhi_s + r * PT + j * 16 + koA));
                LDSM_X4(alo[mt][0], alo[mt][1], alo[mt][2], alo[mt][3],
                        smem_u32(xlo_s + r * PT + j * 16 + koA));
            }
            #pragma unroll
            for (int nt = 0; nt < 8; nt++) {
                int boff = (wc + nt * 8 + (l15 & 7)) * PT + j * 16 + koB;
                unsigned int bh0, bh1, bl0, bl1;
                LDSM_X2(bh0, bh1, smem_u32(whi_s + boff));
                LDSM_X2(bl0, bl1, smem_u32(wlo_s + boff));
                #pragma unroll
                for (int mt = 0; mt < 2; mt++) {
                    MMA16816(acc[mt][nt], ahi[mt][0], ahi[mt][1], ahi[mt][2], ahi[mt][3], bh0, bh1);
                    MMA16816(acc[mt][nt], ahi[mt][0], ahi[mt][1], ahi[mt][2], ahi[mt][3], bl0, bl1);
                    MMA16816(acc[mt][nt], alo[mt][0], alo[mt][1], alo[mt][2], alo[mt][3], bh0, bh1);
                }
            }
        }
        __syncthreads();
    }

    // ---- epilogue: +bias, L2 norm ----
    const int rA = lane >> 2;
    const int cB = (lane & 3) * 2;
    float ssp[2][2];
    #pragma unroll
    for (int mt = 0; mt < 2; mt++) {
        ssp[mt][0] = 0.f; ssp[mt][1] = 0.f;
        #pragma unroll
        for (int nt = 0; nt < 8; nt++) {
            float b0 = b_s[wc + nt * 8 + cB];
            float b1 = b_s[wc + nt * 8 + cB + 1];
            acc[mt][nt][0] += b0; acc[mt][nt][1] += b1;
            acc[mt][nt][2] += b0; acc[mt][nt][3] += b1;
            ssp[mt][0] += acc[mt][nt][0] * acc[mt][nt][0] + acc[mt][nt][1] * acc[mt][nt][1];
            ssp[mt][1] += acc[mt][nt][2] * acc[mt][nt][2] + acc[mt][nt][3] * acc[mt][nt][3];
        }
        #pragma unroll
        for (int d = 1; d < 4; d <<= 1) {
            ssp[mt][0] += __shfl_xor_sync(0xFFFFFFFFu, ssp[mt][0], d);
            ssp[mt][1] += __shfl_xor_sync(0xFFFFFFFFu, ssp[mt][1], d);
        }
        if ((lane & 3) == 0) {
            ss_s[(wr + mt * 16 + rA) * 2 + (w >> 2)]     = ssp[mt][0];
            ss_s[(wr + mt * 16 + rA + 8) * 2 + (w >> 2)] = ssp[mt][1];
        }
    }
    __syncthreads();

    float invA[2], invB[2];
    #pragma unroll
    for (int mt = 0; mt < 2; mt++) {
        int r0l = wr + mt * 16 + rA;
        float ss0 = ss_s[r0l * 2] + ss_s[r0l * 2 + 1];
        float ss1 = ss_s[(r0l + 8) * 2] + ss_s[(r0l + 8) * 2 + 1];
        invA[mt] = 1.f / fmaxf(sqrtf(ss0), 1e-12f);
        invB[mt] = 1.f / fmaxf(sqrtf(ss1), 1e-12f);
    }
    __syncthreads();

    float* xsh = (float*)smem_c;
    #pragma unroll
    for (int mt = 0; mt < 2; mt++) {
        int r0l = wr + mt * 16 + rA;
        int gr = row0 + r0l;
        #pragma unroll
        for (int nt = 0; nt < 8; nt++) {
            int c = wc + nt * 8 + cB;
            float2 v0 = make_float2(fmaxf(acc[mt][nt][0] * invA[mt], 0.f),
                                    fmaxf(acc[mt][nt][1] * invA[mt], 0.f));
            float2 v1 = make_float2(fmaxf(acc[mt][nt][2] * invB[mt], 0.f),
                                    fmaxf(acc[mt][nt][3] * invB[mt], 0.f));
            if (OUT) {
                __half2* A2h = (__half2*)g_acth;
                if (gr < nrows)     A2h[gr * 64 + (c >> 1)]       = __floats2half2_rn(v0.x, v0.y);
                if (gr + 8 < nrows) A2h[(gr + 8) * 64 + (c >> 1)] = __floats2half2_rn(v1.x, v1.y);
            } else {
                if (gr < nrows)     OUText[gr * 64 + (c >> 1)]       = v0;
                if (gr + 8 < nrows) OUText[(gr + 8) * 64 + (c >> 1)] = v1;
                *(float2*)(xsh + r0l * XSH_PITCH + c)       = v0;
                *(float2*)(xsh + (r0l + 8) * XSH_PITCH + c) = v1;
            }
        }
    }

    if (OUT == 0) {
        float4* wsh4 = (float4*)(smem_c + WSH_OFF);
        float*  blsh = (float*)(smem_c + BLSH_OFF);
        for (int i = tid; i < 1280; i += 256) wsh4[i] = Wl4[i];
        if (tid < 40) blsh[tid] = bl[tid];
        __syncthreads();

        int node = tid >> 1;
        int half = tid & 1;
        int gn = row0 + node;

        float lg[20];
        #pragma unroll
        for (int j = 0; j < 20; j++) lg[j] = blsh[half * 20 + j];

        const float4* xrow = (const float4*)(xsh + node * XSH_PITCH);
        #pragma unroll 4
        for (int k4 = 0; k4 < 32; k4++) {
            float4 xvv = xrow[k4];
            float xs[4] = {xvv.x, xvv.y, xvv.z, xvv.w};
            #pragma unroll
            for (int kk = 0; kk < 4; kk++) {
                int k = k4 * 4 + kk;
                const float4* wrow = wsh4 + k * 10 + half * 5;
                #pragma unroll
                for (int c4 = 0; c4 < 5; c4++) {
                    float4 wvv = wrow[c4];
                    lg[c4 * 4 + 0] += xs[kk] * wvv.x;
                    lg[c4 * 4 + 1] += xs[kk] * wvv.y;
                    lg[c4 * 4 + 2] += xs[kk] * wvv.z;
                    lg[c4 * 4 + 3] += xs[kk] * wvv.w;
                }
            }
        }

        float m = -1e30f;
        #pragma unroll
        for (int j = 0; j < 20; j++) m = fmaxf(m, lg[j]);
        m = fmaxf(m, __shfl_xor_sync(0xFFFFFFFFu, m, 1));
        float sum = 0.f;
        float ex[20];
        #pragma unroll
        for (int j = 0; j < 20; j++) { ex[j] = expf(lg[j] - m); sum += ex[j]; }
        sum += __shfl_xor_sync(0xFFFFFFFFu, sum, 1);
        float inv = 1.f / sum;

        if (gn < nrows) {
            int base = gn * NCLASS + half * 20;
            #pragma unroll
            for (int j = 0; j < 20; j++) {
                logits[base + j] = lg[j];
                probs[base + j]  = ex[j] * inv;
            }
        }
    }
}

// ---------------- launch ----------------
extern "C" void kernel_launch(void* const* d_in, const int* in_sizes, int n_in,
                              void* d_out, int out_size) {
    const float* x  = (const float*)d_in[0];
    const int*   ei = (const int*)d_in[1];
    const float* W1 = (const float*)d_in[2];
    const float* b1 = (const float*)d_in[3];
    const float* W2 = (const float*)d_in[4];
    const float* b2 = (const float*)d_in[5];
    const float* W3 = (const float*)d_in[6];
    const float* b3 = (const float*)d_in[7];
    const float* W4 = (const float*)d_in[8];
    const float* b4 = (const float*)d_in[9];
    const float* Wl = (const float*)d_in[10];
    const float* bl = (const float*)d_in[11];

    const int* src = ei;
    const int* dst = ei + N_EDGES;

    float* out    = (float*)d_out;
    float* logits = out;
    float* probs  = out + N_NODES * NCLASS;
    float* x4out  = out + 2 * N_NODES * NCLASS;

    const int T = 256;
    const int gemm_blocks = (N_NODES + 127) / 128;
    const int agg_blocks  = (N_NODES * 32 + T - 1) / T;
    const int hp_blocks   = (N_EDGES + 4 * F * F + N_NODES * F4 + T - 1) / T;
    const int edge_blocks = (N_EDGES + T - 1) / T;

    cudaFuncSetAttribute(gemm_norm_kernel<1>, cudaFuncAttributeMaxDynamicSharedMemorySize, SMEM_L);
    cudaFuncSetAttribute(gemm_norm_kernel<0>, cudaFuncAttributeMaxDynamicSharedMemorySize, SMEM_L0);

    // CSR build + W prep + x->fp16 (one kernel)
    hist_prep_kernel<<<hp_blocks, T>>>(dst, W1, W2, W3, W4, (const float4*)x);
    scan_kernel<<<SCAN_BLKS, 1024>>>();
    fill_kernel<<<edge_blocks, T>>>(src, dst);

    // 4 layers (all-fp16 gathers); layer 4 fuses head
    agg_sum_kernel<0><<<agg_blocks, T>>>();
    gemm_norm_kernel<1><<<gemm_blocks, T, SMEM_L>>>(0, b1, nullptr, N_NODES, nullptr, nullptr, nullptr, nullptr);
    agg_sum_kernel<1><<<agg_blocks, T>>>();
    gemm_norm_kernel<1><<<gemm_blocks, T, SMEM_L>>>(1, b2, nullptr, N_NODES, nullptr, nullptr, nullptr, nullptr);
    agg_sum_kernel<1><<<agg_blocks, T>>>();
    gemm_norm_kernel<1><<<gemm_blocks, T, SMEM_L>>>(2, b3, nullptr, N_NODES, nullptr, nullptr, nullptr, nullptr);
    agg_sum_kernel<1><<<agg_blocks, T>>>();
    gemm_norm_kernel<0><<<gemm_blocks, T, SMEM_L0>>>(3, b4, (float2*)x4out, N_NODES,
                                                     (const float4*)Wl, bl, logits, probs);
}